// round 13
// baseline (speedup 1.0000x reference)
#include <cuda_runtime.h>
#include <cstdint>

#define NPOS    16384
#define NCHUNK  4
#define CHUNK_P (NPOS / NCHUNK)      // 4096
#define SCALEF  0.125f

// -------- scratch (device globals; no allocation allowed) --------
__device__ float g_qk[(size_t)NPOS * 2048];    // 134 MB
__device__ float g_ybar[(size_t)NPOS * 2048];  // 134 MB (tf32-rounded)
__device__ float g_q [(size_t)NPOS * 512];     //  33 MB (tf32-rounded)
__device__ float g_v [(size_t)NPOS * 512];     //  33 MB (tf32-rounded)
__device__ float g_xt[(size_t)NPOS * 256];     //  17 MB (x, tf32-rounded)
__device__ float g_wqs [256 * 512];            // SCALE*Wq, tf32   [k=i][n]
__device__ float g_wkT [8 * 64 * 256];         // Wk^T per head    [h][d][c]
__device__ float g_wvT [8 * 256 * 64];         // Wv per head      [h][c][d]
__device__ float g_wouT[512 * 256];            // Wout, tf32       [k][n]

// ================= TF32 helpers =================
__device__ __forceinline__ float f2tf(float x) {
    uint32_t u;
    asm("cvt.rna.tf32.f32 %0, %1;" : "=r"(u) : "f"(x));
    return __uint_as_float(u);
}

__device__ __forceinline__ void mma8(float* d, const uint32_t* a, const uint32_t* b) {
    asm volatile(
        "mma.sync.aligned.m16n8k8.row.col.f32.tf32.tf32.f32 "
        "{%0,%1,%2,%3}, {%4,%5,%6,%7}, {%8,%9}, {%0,%1,%2,%3};"
        : "+f"(d[0]), "+f"(d[1]), "+f"(d[2]), "+f"(d[3])
        : "r"(a[0]), "r"(a[1]), "r"(a[2]), "r"(a[3]), "r"(b[0]), "r"(b[1]));
}

__device__ __forceinline__ void cpasync16(uint32_t s, const void* g) {
    asm volatile("cp.async.cg.shared.global [%0], [%1], 16;" :: "r"(s), "l"(g));
}

// ================= merged prep kernel =================
__global__ __launch_bounds__(256)
void prep_all(const float* __restrict__ Wq, const float* __restrict__ Wkv,
              const float* __restrict__ Wout, const float* __restrict__ x,
              float* __restrict__ wqs, float* __restrict__ wkT,
              float* __restrict__ wvT, float* __restrict__ wouT,
              float* __restrict__ xt)
{
    if (blockIdx.x < 2048) {
        int idx = blockIdx.x * 256 + threadIdx.x;
        int sel = idx >> 17;
        int r = idx & 131071;
        if (sel == 0) {
            wqs[r] = f2tf(SCALEF * Wq[r]);
        } else if (sel == 1) {
            int h = r >> 14, d = (r >> 8) & 63, c = r & 255;
            wkT[r] = f2tf(Wkv[c * 1024 + h * 64 + d]);
        } else if (sel == 2) {
            int h = r >> 14, c = (r >> 6) & 255, d = r & 63;
            wvT[r] = f2tf(Wkv[c * 1024 + 512 + h * 64 + d]);
        } else {
            wouT[r] = f2tf(Wout[r]);
        }
    } else {
        int i = (blockIdx.x - 2048) * 256 + threadIdx.x;   // per float4
        float4 v = ((const float4*)x)[i];
        v.x = f2tf(v.x); v.y = f2tf(v.y); v.z = f2tf(v.z); v.w = f2tf(v.w);
        ((float4*)xt)[i] = v;
    }
}

// ================= TF32 GEMM (generic, 2-stage cp.async) ====================
#define BM 128
#define BK 32
#define ASTR 36
#define A_FLOATS (BM * ASTR)        // 4608

template<int BNT>
__global__ __launch_bounds__(256, 2)
void gemm4(const float* __restrict__ A, const float* __restrict__ B,
           float* __restrict__ C, const float* __restrict__ bias,
           int K, int lda, int ldb, int ldc,
           long long aB, long long bB, long long cB, int doRound)
{
    constexpr int BSTR = BNT + 8;
    constexpr int B_FLOATS = BK * BSTR;
    constexpr int STAGEF = A_FLOATS + B_FLOATS;
    constexpr int MI = (BNT == 128) ? 4 : 2;
    constexpr int BN4 = BNT / 4;
    constexpr int NB_I = (BK * BN4) / 256;

    extern __shared__ float sm[];

    const int t = threadIdx.x;
    const int lane = t & 31, wid = t >> 5;
    const int g = lane >> 2, tig = lane & 3;
    const int wm = (BNT == 128) ? (wid & 1) * 64 : (wid & 3) * 32;
    const int wn = (BNT == 128) ? (wid >> 1) * 32 : (wid >> 2) * 32;
    const long long bm = (long long)blockIdx.x * BM;
    const long long bn = (long long)blockIdx.y * BNT;

    const float* Ab = A + (long long)blockIdx.z * aB;
    const float* Bb = B + (long long)blockIdx.z * bB + bn;
    float*       Cb = C + (long long)blockIdx.z * cB;

    uint32_t sA[2], sB[2];
#pragma unroll
    for (int s = 0; s < 2; s++) {
        sA[s] = (uint32_t)__cvta_generic_to_shared(sm + s * STAGEF);
        sB[s] = (uint32_t)__cvta_generic_to_shared(sm + s * STAGEF + A_FLOATS);
    }

    float acc[MI][4][4];
#pragma unroll
    for (int i = 0; i < MI; i++)
#pragma unroll
        for (int j = 0; j < 4; j++)
#pragma unroll
            for (int q = 0; q < 4; q++) acc[i][j][q] = 0.f;

    const int ntiles = K / BK;

#pragma unroll
    for (int i = 0; i < 4; i++) {
        int idx = i * 256 + t;
        int r = idx >> 3, c4 = idx & 7;
        cpasync16(sA[0] + (r * ASTR + c4 * 4) * 4, Ab + (bm + r) * lda + c4 * 4);
    }
#pragma unroll
    for (int i = 0; i < NB_I; i++) {
        int idx = i * 256 + t;
        int k = idx / BN4, n4 = idx % BN4;
        cpasync16(sB[0] + (k * BSTR + n4 * 4) * 4, Bb + (long long)k * ldb + n4 * 4);
    }
    asm volatile("cp.async.commit_group;");

    for (int it = 0; it < ntiles; it++) {
        const int buf = it & 1;
        if (it + 1 < ntiles) {
            const int nb = buf ^ 1;
            const long long ko = (long long)(it + 1) * BK;
#pragma unroll
            for (int i = 0; i < 4; i++) {
                int idx = i * 256 + t;
                int r = idx >> 3, c4 = idx & 7;
                cpasync16(sA[nb] + (r * ASTR + c4 * 4) * 4,
                          Ab + (bm + r) * lda + ko + c4 * 4);
            }
#pragma unroll
            for (int i = 0; i < NB_I; i++) {
                int idx = i * 256 + t;
                int k = idx / BN4, n4 = idx % BN4;
                cpasync16(sB[nb] + (k * BSTR + n4 * 4) * 4,
                          Bb + (ko + k) * ldb + n4 * 4);
            }
            asm volatile("cp.async.commit_group;");
            asm volatile("cp.async.wait_group 1;");
        } else {
            asm volatile("cp.async.wait_group 0;");
        }
        __syncthreads();

        const float* as = sm + buf * STAGEF;
        const float* bs = as + A_FLOATS;
#pragma unroll
        for (int ks = 0; ks < 4; ks++) {
            const int k0 = ks * 8;
            uint32_t af[MI][4], bf[4][2];
#pragma unroll
            for (int mi = 0; mi < MI; mi++) {
                const int r = wm + mi * 16 + g;
                af[mi][0] = __float_as_uint(as[r * ASTR + k0 + tig]);
                af[mi][1] = __float_as_uint(as[(r + 8) * ASTR + k0 + tig]);
                af[mi][2] = __float_as_uint(as[r * ASTR + k0 + tig + 4]);
                af[mi][3] = __float_as_uint(as[(r + 8) * ASTR + k0 + tig + 4]);
            }
#pragma unroll
            for (int ni = 0; ni < 4; ni++) {
                const int cn = wn + ni * 8 + g;
                bf[ni][0] = __float_as_uint(bs[(k0 + tig) * BSTR + cn]);
                bf[ni][1] = __float_as_uint(bs[(k0 + tig + 4) * BSTR + cn]);
            }
#pragma unroll
            for (int mi = 0; mi < MI; mi++)
#pragma unroll
                for (int ni = 0; ni < 4; ni++)
                    mma8(acc[mi][ni], af[mi], bf[ni]);
        }
        __syncthreads();
    }

#pragma unroll
    for (int mi = 0; mi < MI; mi++) {
#pragma unroll
        for (int ni = 0; ni < 4; ni++) {
            const long long r = bm + wm + mi * 16 + g;
            const int cn = (int)bn + wn + ni * 8 + 2 * tig;
            float v0 = acc[mi][ni][0], v1 = acc[mi][ni][1];
            float v2 = acc[mi][ni][2], v3 = acc[mi][ni][3];
            if (bias) {
                float b0 = bias[cn], b1 = bias[cn + 1];
                v0 += b0; v1 += b1; v2 += b0; v3 += b1;
            }
            if (doRound) {
                v0 = f2tf(v0); v1 = f2tf(v1); v2 = f2tf(v2); v3 = f2tf(v3);
            }
            *(float2*)(Cb + r * ldc + cn)       = make_float2(v0, v1);
            *(float2*)(Cb + (r + 8) * ldc + cn) = make_float2(v2, v3);
        }
    }
}

// ================= single-shot K=64 GEMM (G2) ================================
#define K64_ASTR 68
#define K64_BSTR 136
#define K64_AF (64 * K64_ASTR)
#define K64_BF (64 * K64_BSTR)
#define K64_SMEM ((K64_AF + K64_BF) * 4)   // 52224 bytes

__global__ __launch_bounds__(256, 3)
void gemm_k64(const float* __restrict__ A, const float* __restrict__ B,
              float* __restrict__ C,
              int lda, int ldb, int ldc,
              long long aB, long long bB, long long cB)
{
    extern __shared__ float sm[];
    float* As = sm;
    float* Bs = sm + K64_AF;

    const int t = threadIdx.x;
    const int lane = t & 31, wid = t >> 5;
    const int g = lane >> 2, tig = lane & 3;
    const int wm = (wid & 1) * 32;
    const int wn = (wid >> 1) * 32;
    const long long bm = (long long)blockIdx.x * 64;
    const long long bn = (long long)blockIdx.y * 128;

    const float* Ab = A + (long long)blockIdx.z * aB;
    const float* Bb = B + (long long)blockIdx.z * bB + bn;
    float*       Cb = C + (long long)blockIdx.z * cB;

    uint32_t sAs = (uint32_t)__cvta_generic_to_shared(As);
    uint32_t sBs = (uint32_t)__cvta_generic_to_shared(Bs);

#pragma unroll
    for (int i = 0; i < 4; i++) {
        int idx = i * 256 + t;
        int r = idx >> 4, c4 = idx & 15;
        cpasync16(sAs + (r * K64_ASTR + c4 * 4) * 4, Ab + (bm + r) * lda + c4 * 4);
    }
#pragma unroll
    for (int i = 0; i < 8; i++) {
        int idx = i * 256 + t;
        int k = idx >> 5, n4 = idx & 31;
        cpasync16(sBs + (k * K64_BSTR + n4 * 4) * 4, Bb + (long long)k * ldb + n4 * 4);
    }
    asm volatile("cp.async.commit_group;");
    asm volatile("cp.async.wait_group 0;");
    __syncthreads();

    float acc[2][4][4];
#pragma unroll
    for (int i = 0; i < 2; i++)
#pragma unroll
        for (int j = 0; j < 4; j++)
#pragma unroll
            for (int q = 0; q < 4; q++) acc[i][j][q] = 0.f;

#pragma unroll
    for (int ks = 0; ks < 8; ks++) {
        const int k0 = ks * 8;
        uint32_t af[2][4], bf[4][2];
#pragma unroll
        for (int mi = 0; mi < 2; mi++) {
            const int r = wm + mi * 16 + g;
            af[mi][0] = __float_as_uint(As[r * K64_ASTR + k0 + tig]);
            af[mi][1] = __float_as_uint(As[(r + 8) * K64_ASTR + k0 + tig]);
            af[mi][2] = __float_as_uint(As[r * K64_ASTR + k0 + tig + 4]);
            af[mi][3] = __float_as_uint(As[(r + 8) * K64_ASTR + k0 + tig + 4]);
        }
#pragma unroll
        for (int ni = 0; ni < 4; ni++) {
            const int cn = wn + ni * 8 + g;
            bf[ni][0] = __float_as_uint(Bs[(k0 + tig) * K64_BSTR + cn]);
            bf[ni][1] = __float_as_uint(Bs[(k0 + tig + 4) * K64_BSTR + cn]);
        }
#pragma unroll
        for (int mi = 0; mi < 2; mi++)
#pragma unroll
            for (int ni = 0; ni < 4; ni++)
                mma8(acc[mi][ni], af[mi], bf[ni]);
    }

#pragma unroll
    for (int mi = 0; mi < 2; mi++) {
#pragma unroll
        for (int ni = 0; ni < 4; ni++) {
            const long long r = bm + wm + mi * 16 + g;
            const int cn = (int)bn + wn + ni * 8 + 2 * tig;
            *(float2*)(Cb + r * ldc + cn) =
                make_float2(acc[mi][ni][0], acc[mi][ni][1]);
            *(float2*)(Cb + (r + 8) * ldc + cn) =
                make_float2(acc[mi][ni][2], acc[mi][ni][3]);
        }
    }
}

// ================= fused attention v5: 2 positions per CTA ====================
#define YP 260
#define YS_F (16 * YP)
#define QS_F (8 * YP)
#define ATTN_SMEM ((2 * YS_F + 2 * QS_F + 2 * 512 + 2 * 128) * 4)   // 55040 B

__global__ __launch_bounds__(256)
void attn5(const float* __restrict__ y, const float* __restrict__ qk,
           float* __restrict__ ybar)
{
    extern __shared__ float smb[];
    const int s  = threadIdx.x >> 7;
    const int t  = threadIdx.x & 127;

    float* ys     = smb + s * YS_F;
    float* qs     = smb + 2 * YS_F + s * QS_F;
    float* part   = smb + 2 * YS_F + 2 * QS_F + s * 512;
    float* attn_s = smb + 2 * YS_F + 2 * QS_F + 2 * 512 + s * 128;

    const long long p = (long long)blockIdx.x * 2 + s;
    const float* yg = y  + p * 4096;
    const float* qg = qk + p * 2048;

#pragma unroll
    for (int i = 0; i < 8; i++) {
        int idx4 = i * 128 + t;
        int m = idx4 >> 6, c = (idx4 & 63) * 4;
        cpasync16((uint32_t)__cvta_generic_to_shared(ys + m * YP + c), yg + idx4 * 4);
    }
#pragma unroll
    for (int i = 0; i < 4; i++) {
        int idx4 = i * 128 + t;
        int h = idx4 >> 6, c = (idx4 & 63) * 4;
        cpasync16((uint32_t)__cvta_generic_to_shared(qs + h * YP + c), qg + idx4 * 4);
    }
    asm volatile("cp.async.commit_group;");
    asm volatile("cp.async.wait_group 0;");
    __syncthreads();

    const int lane = t & 31, w = t >> 5;
    const int g = lane >> 2, tig = lane & 3;

    float acc[4] = {0.f, 0.f, 0.f, 0.f};
#pragma unroll
    for (int cc = 0; cc < 8; cc++) {
        const int c0 = w * 64 + cc * 8;
        float a[4], b[2];
        a[0] = ys[g * YP + c0 + tig];
        a[1] = ys[(g + 8) * YP + c0 + tig];
        a[2] = ys[g * YP + c0 + tig + 4];
        a[3] = ys[(g + 8) * YP + c0 + tig + 4];
        b[0] = qs[g * YP + c0 + tig];
        b[1] = qs[g * YP + c0 + tig + 4];

        uint32_t ah[4], al[4], bh[2], bl[2];
#pragma unroll
        for (int i = 0; i < 4; i++) {
            float hi = f2tf(a[i]);
            ah[i] = __float_as_uint(hi);
            al[i] = __float_as_uint(f2tf(a[i] - hi));
        }
#pragma unroll
        for (int i = 0; i < 2; i++) {
            float hi = f2tf(b[i]);
            bh[i] = __float_as_uint(hi);
            bl[i] = __float_as_uint(f2tf(b[i] - hi));
        }
        mma8(acc, ah, bh);
        mma8(acc, al, bh);
        mma8(acc, ah, bl);
    }
    part[w * 128 + g * 8 + 2 * tig]           = acc[0];
    part[w * 128 + g * 8 + 2 * tig + 1]       = acc[1];
    part[w * 128 + (g + 8) * 8 + 2 * tig]     = acc[2];
    part[w * 128 + (g + 8) * 8 + 2 * tig + 1] = acc[3];
    __syncthreads();

    const int h = t >> 4, m = t & 15;
    float dot = part[0 * 128 + m * 8 + h] + part[1 * 128 + m * 8 + h]
              + part[2 * 128 + m * 8 + h] + part[3 * 128 + m * 8 + h];

    float mx = dot;
#pragma unroll
    for (int o = 8; o >= 1; o >>= 1)
        mx = fmaxf(mx, __shfl_xor_sync(0xffffffffu, mx, o));
    float e = __expf(dot - mx);
    float sum = e;
#pragma unroll
    for (int o = 8; o >= 1; o >>= 1)
        sum += __shfl_xor_sync(0xffffffffu, sum, o);
    attn_s[m * 8 + h] = e / sum;
    __syncthreads();

    const int c0 = 2 * t;
    float2 acc2[8];
#pragma unroll
    for (int i = 0; i < 8; i++) acc2[i] = make_float2(0.f, 0.f);

#pragma unroll
    for (int mm = 0; mm < 16; mm++) {
        float4 a0 = *(const float4*)(attn_s + mm * 8);
        float4 a1 = *(const float4*)(attn_s + mm * 8 + 4);
        float2 yv = *(const float2*)(ys + mm * YP + c0);
        acc2[0].x = fmaf(a0.x, yv.x, acc2[0].x); acc2[0].y = fmaf(a0.x, yv.y, acc2[0].y);
        acc2[1].x = fmaf(a0.y, yv.x, acc2[1].x); acc2[1].y = fmaf(a0.y, yv.y, acc2[1].y);
        acc2[2].x = fmaf(a0.z, yv.x, acc2[2].x); acc2[2].y = fmaf(a0.z, yv.y, acc2[2].y);
        acc2[3].x = fmaf(a0.w, yv.x, acc2[3].x); acc2[3].y = fmaf(a0.w, yv.y, acc2[3].y);
        acc2[4].x = fmaf(a1.x, yv.x, acc2[4].x); acc2[4].y = fmaf(a1.x, yv.y, acc2[4].y);
        acc2[5].x = fmaf(a1.y, yv.x, acc2[5].x); acc2[5].y = fmaf(a1.y, yv.y, acc2[5].y);
        acc2[6].x = fmaf(a1.z, yv.x, acc2[6].x); acc2[6].y = fmaf(a1.z, yv.y, acc2[6].y);
        acc2[7].x = fmaf(a1.w, yv.x, acc2[7].x); acc2[7].y = fmaf(a1.w, yv.y, acc2[7].y);
    }

    float* op = ybar + p * 2048 + c0;
#pragma unroll
    for (int hh = 0; hh < 8; hh++) {
        float2 v = make_float2(f2tf(acc2[hh].x), f2tf(acc2[hh].y));
        *(float2*)(op + hh * 256) = v;
    }
}

// ================= launch: 4 chunks over 2 streams =================
extern "C" void kernel_launch(void* const* d_in, const int* in_sizes, int n_in,
                              void* d_out, int out_size)
{
    const float* x     = (const float*)d_in[0];
    const float* y     = (const float*)d_in[1];
    const float* W_q   = (const float*)d_in[2];
    const float* W_kv  = (const float*)d_in[3];
    const float* W_out = (const float*)d_in[4];
    const float* b_out = (const float*)d_in[5];
    float* out = (float*)d_out;

    float *qk, *ybar, *q, *v, *xt, *wqs, *wkT, *wvT, *wouT;
    cudaGetSymbolAddress((void**)&qk,   g_qk);
    cudaGetSymbolAddress((void**)&ybar, g_ybar);
    cudaGetSymbolAddress((void**)&q,    g_q);
    cudaGetSymbolAddress((void**)&v,    g_v);
    cudaGetSymbolAddress((void**)&xt,   g_xt);
    cudaGetSymbolAddress((void**)&wqs,  g_wqs);
    cudaGetSymbolAddress((void**)&wkT,  g_wkT);
    cudaGetSymbolAddress((void**)&wvT,  g_wvT);
    cudaGetSymbolAddress((void**)&wouT, g_wouT);

    const int SM128 = 2 * (A_FLOATS + BK * (128 + 8)) * 4;   // 71680
    const int SM64  = 2 * (A_FLOATS + BK * (64 + 8)) * 4;    // 55296
    cudaFuncSetAttribute(gemm4<128>, cudaFuncAttributeMaxDynamicSharedMemorySize, SM128);
    cudaFuncSetAttribute(gemm4<64>,  cudaFuncAttributeMaxDynamicSharedMemorySize, SM64);
    cudaFuncSetAttribute(gemm_k64, cudaFuncAttributeMaxDynamicSharedMemorySize, K64_SMEM);
    cudaFuncSetAttribute(attn5, cudaFuncAttributeMaxDynamicSharedMemorySize, ATTN_SMEM);

    // fork-join streams (created per call; no device-memory allocation involved)
    cudaStream_t s2;
    cudaEvent_t evPrep, evDone;
    cudaStreamCreateWithFlags(&s2, cudaStreamNonBlocking);
    cudaEventCreateWithFlags(&evPrep, cudaEventDisableTiming);
    cudaEventCreateWithFlags(&evDone, cudaEventDisableTiming);

    // P0 on main stream
    prep_all<<<6144, 256>>>(W_q, W_kv, W_out, x, wqs, wkT, wvT, wouT, xt);
    cudaEventRecord(evPrep, 0);
    cudaStreamWaitEvent(s2, evPrep, 0);

    // ---- 4 chunk-chains, interleaved across 2 streams ----
    for (int c = 0; c < NCHUNK; c++) {
        cudaStream_t st = (c & 1) ? s2 : (cudaStream_t)0;
        const long long po = (long long)c * CHUNK_P;

        const float* xt_h   = xt   + po * 256;
        float*       q_h    = q    + po * 512;
        float*       qk_h   = qk   + po * 2048;
        const float* y_h    = y    + po * 4096;
        float*       ybar_h = ybar + po * 2048;
        float*       v_h    = v    + po * 512;
        float*       out_h  = out  + po * 256;

        // G1: q = xt @ wqs   (M=4096, N=512, K=256), round out
        gemm4<128><<<dim3(32, 4, 1), 256, SM128, st>>>(xt_h, wqs, q_h, nullptr,
                                                       256, 256, 512, 512, 0, 0, 0, 1);

        // G2: qk_h = q_h @ Wk_h^T  (per head: M=4096, N=256, K=64)
        gemm_k64<<<dim3(64, 2, 8), 256, K64_SMEM, st>>>(q_h, wkT, qk_h,
                                                        512, 256, 2048,
                                                        64, 16384, 256);

        // attn: dots -> softmax -> ybar (tf32-rounded), 2 positions per CTA
        attn5<<<CHUNK_P / 2, 256, ATTN_SMEM, st>>>(y_h, qk_h, ybar_h);

        // G3: v_h = ybar_h @ Wv_h  (per head: M=4096, N=64, K=256), round out
        gemm4<64><<<dim3(32, 1, 8), 256, SM64, st>>>(ybar_h, wvT, v_h, nullptr,
                                                     256, 2048, 64, 512,
                                                     256, 16384, 64, 1);

        // G4: out = v @ wouT + b_out  (M=4096, N=256, K=512)
        gemm4<128><<<dim3(32, 2, 1), 256, SM128, st>>>(v_h, wouT, out_h, b_out,
                                                       512, 512, 256, 256, 0, 0, 0, 0);
    }

    // join: main stream waits for s2's chains
    cudaEventRecord(evDone, s2);
    cudaStreamWaitEvent(0, evDone, 0);
}

// round 14
// speedup vs baseline: 1.2831x; 1.2831x over previous
#include <cuda_runtime.h>
#include <cstdint>

#define NPOS   16384
#define HALF_P (NPOS / 2)
#define SCALEF 0.125f

// -------- scratch (device globals; no allocation allowed) --------
__device__ float g_qk[(size_t)NPOS * 2048];    // 134 MB
__device__ float g_ybar[(size_t)NPOS * 2048];  // 134 MB (tf32-rounded)
__device__ float g_q [(size_t)NPOS * 512];     //  33 MB (tf32-rounded)
__device__ float g_v [(size_t)NPOS * 512];     //  33 MB (tf32-rounded)
__device__ float g_xt[(size_t)NPOS * 256];     //  17 MB (x, tf32-rounded)
__device__ float g_wqs [256 * 512];            // SCALE*Wq, tf32   [k=i][n]
__device__ float g_wkT [8 * 64 * 256];         // Wk^T per head    [h][d][c]
__device__ float g_wvT [8 * 256 * 64];         // Wv per head      [h][c][d]
__device__ float g_wouT[512 * 256];            // Wout, tf32       [k][n]

// ================= TF32 helpers =================
__device__ __forceinline__ float f2tf(float x) {
    uint32_t u;
    asm("cvt.rna.tf32.f32 %0, %1;" : "=r"(u) : "f"(x));
    return __uint_as_float(u);
}

__device__ __forceinline__ void mma8(float* d, const uint32_t* a, const uint32_t* b) {
    asm volatile(
        "mma.sync.aligned.m16n8k8.row.col.f32.tf32.tf32.f32 "
        "{%0,%1,%2,%3}, {%4,%5,%6,%7}, {%8,%9}, {%0,%1,%2,%3};"
        : "+f"(d[0]), "+f"(d[1]), "+f"(d[2]), "+f"(d[3])
        : "r"(a[0]), "r"(a[1]), "r"(a[2]), "r"(a[3]), "r"(b[0]), "r"(b[1]));
}

__device__ __forceinline__ void cpasync16(uint32_t s, const void* g) {
    asm volatile("cp.async.cg.shared.global [%0], [%1], 16;" :: "r"(s), "l"(g));
}

// ================= merged prep kernel =================
__global__ __launch_bounds__(256)
void prep_all(const float* __restrict__ Wq, const float* __restrict__ Wkv,
              const float* __restrict__ Wout, const float* __restrict__ x,
              float* __restrict__ wqs, float* __restrict__ wkT,
              float* __restrict__ wvT, float* __restrict__ wouT,
              float* __restrict__ xt)
{
    if (blockIdx.x < 2048) {
        int idx = blockIdx.x * 256 + threadIdx.x;
        int sel = idx >> 17;
        int r = idx & 131071;
        if (sel == 0) {
            wqs[r] = f2tf(SCALEF * Wq[r]);
        } else if (sel == 1) {
            int h = r >> 14, d = (r >> 8) & 63, c = r & 255;
            wkT[r] = f2tf(Wkv[c * 1024 + h * 64 + d]);
        } else if (sel == 2) {
            int h = r >> 14, c = (r >> 6) & 255, d = r & 63;
            wvT[r] = f2tf(Wkv[c * 1024 + 512 + h * 64 + d]);
        } else {
            wouT[r] = f2tf(Wout[r]);
        }
    } else {
        int i = (blockIdx.x - 2048) * 256 + threadIdx.x;   // per float4
        float4 v = ((const float4*)x)[i];
        v.x = f2tf(v.x); v.y = f2tf(v.y); v.z = f2tf(v.z); v.w = f2tf(v.w);
        ((float4*)xt)[i] = v;
    }
}

// ================= TF32 GEMM (generic, 2-stage cp.async) ====================
#define BM 128
#define BK 32
#define ASTR 36
#define A_FLOATS (BM * ASTR)        // 4608

template<int BNT>
__global__ __launch_bounds__(256, 2)
void gemm4(const float* __restrict__ A, const float* __restrict__ B,
           float* __restrict__ C, const float* __restrict__ bias,
           int K, int lda, int ldb, int ldc,
           long long aB, long long bB, long long cB, int doRound)
{
    constexpr int BSTR = BNT + 8;
    constexpr int B_FLOATS = BK * BSTR;
    constexpr int STAGEF = A_FLOATS + B_FLOATS;
    constexpr int MI = (BNT == 128) ? 4 : 2;
    constexpr int BN4 = BNT / 4;
    constexpr int NB_I = (BK * BN4) / 256;

    extern __shared__ float sm[];

    const int t = threadIdx.x;
    const int lane = t & 31, wid = t >> 5;
    const int g = lane >> 2, tig = lane & 3;
    const int wm = (BNT == 128) ? (wid & 1) * 64 : (wid & 3) * 32;
    const int wn = (BNT == 128) ? (wid >> 1) * 32 : (wid >> 2) * 32;
    const long long bm = (long long)blockIdx.x * BM;
    const long long bn = (long long)blockIdx.y * BNT;

    const float* Ab = A + (long long)blockIdx.z * aB;
    const float* Bb = B + (long long)blockIdx.z * bB + bn;
    float*       Cb = C + (long long)blockIdx.z * cB;

    uint32_t sA[2], sB[2];
#pragma unroll
    for (int s = 0; s < 2; s++) {
        sA[s] = (uint32_t)__cvta_generic_to_shared(sm + s * STAGEF);
        sB[s] = (uint32_t)__cvta_generic_to_shared(sm + s * STAGEF + A_FLOATS);
    }

    float acc[MI][4][4];
#pragma unroll
    for (int i = 0; i < MI; i++)
#pragma unroll
        for (int j = 0; j < 4; j++)
#pragma unroll
            for (int q = 0; q < 4; q++) acc[i][j][q] = 0.f;

    const int ntiles = K / BK;

#pragma unroll
    for (int i = 0; i < 4; i++) {
        int idx = i * 256 + t;
        int r = idx >> 3, c4 = idx & 7;
        cpasync16(sA[0] + (r * ASTR + c4 * 4) * 4, Ab + (bm + r) * lda + c4 * 4);
    }
#pragma unroll
    for (int i = 0; i < NB_I; i++) {
        int idx = i * 256 + t;
        int k = idx / BN4, n4 = idx % BN4;
        cpasync16(sB[0] + (k * BSTR + n4 * 4) * 4, Bb + (long long)k * ldb + n4 * 4);
    }
    asm volatile("cp.async.commit_group;");

    for (int it = 0; it < ntiles; it++) {
        const int buf = it & 1;
        if (it + 1 < ntiles) {
            const int nb = buf ^ 1;
            const long long ko = (long long)(it + 1) * BK;
#pragma unroll
            for (int i = 0; i < 4; i++) {
                int idx = i * 256 + t;
                int r = idx >> 3, c4 = idx & 7;
                cpasync16(sA[nb] + (r * ASTR + c4 * 4) * 4,
                          Ab + (bm + r) * lda + ko + c4 * 4);
            }
#pragma unroll
            for (int i = 0; i < NB_I; i++) {
                int idx = i * 256 + t;
                int k = idx / BN4, n4 = idx % BN4;
                cpasync16(sB[nb] + (k * BSTR + n4 * 4) * 4,
                          Bb + (ko + k) * ldb + n4 * 4);
            }
            asm volatile("cp.async.commit_group;");
            asm volatile("cp.async.wait_group 1;");
        } else {
            asm volatile("cp.async.wait_group 0;");
        }
        __syncthreads();

        const float* as = sm + buf * STAGEF;
        const float* bs = as + A_FLOATS;
#pragma unroll
        for (int ks = 0; ks < 4; ks++) {
            const int k0 = ks * 8;
            uint32_t af[MI][4], bf[4][2];
#pragma unroll
            for (int mi = 0; mi < MI; mi++) {
                const int r = wm + mi * 16 + g;
                af[mi][0] = __float_as_uint(as[r * ASTR + k0 + tig]);
                af[mi][1] = __float_as_uint(as[(r + 8) * ASTR + k0 + tig]);
                af[mi][2] = __float_as_uint(as[r * ASTR + k0 + tig + 4]);
                af[mi][3] = __float_as_uint(as[(r + 8) * ASTR + k0 + tig + 4]);
            }
#pragma unroll
            for (int ni = 0; ni < 4; ni++) {
                const int cn = wn + ni * 8 + g;
                bf[ni][0] = __float_as_uint(bs[(k0 + tig) * BSTR + cn]);
                bf[ni][1] = __float_as_uint(bs[(k0 + tig + 4) * BSTR + cn]);
            }
#pragma unroll
            for (int mi = 0; mi < MI; mi++)
#pragma unroll
                for (int ni = 0; ni < 4; ni++)
                    mma8(acc[mi][ni], af[mi], bf[ni]);
        }
        __syncthreads();
    }

#pragma unroll
    for (int mi = 0; mi < MI; mi++) {
#pragma unroll
        for (int ni = 0; ni < 4; ni++) {
            const long long r = bm + wm + mi * 16 + g;
            const int cn = (int)bn + wn + ni * 8 + 2 * tig;
            float v0 = acc[mi][ni][0], v1 = acc[mi][ni][1];
            float v2 = acc[mi][ni][2], v3 = acc[mi][ni][3];
            if (bias) {
                float b0 = bias[cn], b1 = bias[cn + 1];
                v0 += b0; v1 += b1; v2 += b0; v3 += b1;
            }
            if (doRound) {
                v0 = f2tf(v0); v1 = f2tf(v1); v2 = f2tf(v2); v3 = f2tf(v3);
            }
            *(float2*)(Cb + r * ldc + cn)       = make_float2(v0, v1);
            *(float2*)(Cb + (r + 8) * ldc + cn) = make_float2(v2, v3);
        }
    }
}

// ================= single-shot K=64 GEMM (G2) ================================
#define K64_ASTR 68
#define K64_BSTR 136
#define K64_AF (64 * K64_ASTR)
#define K64_BF (64 * K64_BSTR)
#define K64_SMEM ((K64_AF + K64_BF) * 4)   // 52224 bytes

__global__ __launch_bounds__(256, 3)
void gemm_k64(const float* __restrict__ A, const float* __restrict__ B,
              float* __restrict__ C,
              int lda, int ldb, int ldc,
              long long aB, long long bB, long long cB)
{
    extern __shared__ float sm[];
    float* As = sm;
    float* Bs = sm + K64_AF;

    const int t = threadIdx.x;
    const int lane = t & 31, wid = t >> 5;
    const int g = lane >> 2, tig = lane & 3;
    const int wm = (wid & 1) * 32;
    const int wn = (wid >> 1) * 32;
    const long long bm = (long long)blockIdx.x * 64;
    const long long bn = (long long)blockIdx.y * 128;

    const float* Ab = A + (long long)blockIdx.z * aB;
    const float* Bb = B + (long long)blockIdx.z * bB + bn;
    float*       Cb = C + (long long)blockIdx.z * cB;

    uint32_t sAs = (uint32_t)__cvta_generic_to_shared(As);
    uint32_t sBs = (uint32_t)__cvta_generic_to_shared(Bs);

#pragma unroll
    for (int i = 0; i < 4; i++) {
        int idx = i * 256 + t;
        int r = idx >> 4, c4 = idx & 15;
        cpasync16(sAs + (r * K64_ASTR + c4 * 4) * 4, Ab + (bm + r) * lda + c4 * 4);
    }
#pragma unroll
    for (int i = 0; i < 8; i++) {
        int idx = i * 256 + t;
        int k = idx >> 5, n4 = idx & 31;
        cpasync16(sBs + (k * K64_BSTR + n4 * 4) * 4, Bb + (long long)k * ldb + n4 * 4);
    }
    asm volatile("cp.async.commit_group;");
    asm volatile("cp.async.wait_group 0;");
    __syncthreads();

    float acc[2][4][4];
#pragma unroll
    for (int i = 0; i < 2; i++)
#pragma unroll
        for (int j = 0; j < 4; j++)
#pragma unroll
            for (int q = 0; q < 4; q++) acc[i][j][q] = 0.f;

#pragma unroll
    for (int ks = 0; ks < 8; ks++) {
        const int k0 = ks * 8;
        uint32_t af[2][4], bf[4][2];
#pragma unroll
        for (int mi = 0; mi < 2; mi++) {
            const int r = wm + mi * 16 + g;
            af[mi][0] = __float_as_uint(As[r * K64_ASTR + k0 + tig]);
            af[mi][1] = __float_as_uint(As[(r + 8) * K64_ASTR + k0 + tig]);
            af[mi][2] = __float_as_uint(As[r * K64_ASTR + k0 + tig + 4]);
            af[mi][3] = __float_as_uint(As[(r + 8) * K64_ASTR + k0 + tig + 4]);
        }
#pragma unroll
        for (int ni = 0; ni < 4; ni++) {
            const int cn = wn + ni * 8 + g;
            bf[ni][0] = __float_as_uint(Bs[(k0 + tig) * K64_BSTR + cn]);
            bf[ni][1] = __float_as_uint(Bs[(k0 + tig + 4) * K64_BSTR + cn]);
        }
#pragma unroll
        for (int mi = 0; mi < 2; mi++)
#pragma unroll
            for (int ni = 0; ni < 4; ni++)
                mma8(acc[mi][ni], af[mi], bf[ni]);
    }

#pragma unroll
    for (int mi = 0; mi < 2; mi++) {
#pragma unroll
        for (int ni = 0; ni < 4; ni++) {
            const long long r = bm + wm + mi * 16 + g;
            const int cn = (int)bn + wn + ni * 8 + 2 * tig;
            *(float2*)(Cb + r * ldc + cn) =
                make_float2(acc[mi][ni][0], acc[mi][ni][1]);
            *(float2*)(Cb + (r + 8) * ldc + cn) =
                make_float2(acc[mi][ni][2], acc[mi][ni][3]);
        }
    }
}

// ================= fused attention v5: 2 positions per CTA ====================
#define YP 260
#define YS_F (16 * YP)
#define QS_F (8 * YP)
#define ATTN_SMEM ((2 * YS_F + 2 * QS_F + 2 * 512 + 2 * 128) * 4)   // 55040 B

__global__ __launch_bounds__(256)
void attn5(const float* __restrict__ y, const float* __restrict__ qk,
           float* __restrict__ ybar)
{
    extern __shared__ float smb[];
    const int s  = threadIdx.x >> 7;
    const int t  = threadIdx.x & 127;

    float* ys     = smb + s * YS_F;
    float* qs     = smb + 2 * YS_F + s * QS_F;
    float* part   = smb + 2 * YS_F + 2 * QS_F + s * 512;
    float* attn_s = smb + 2 * YS_F + 2 * QS_F + 2 * 512 + s * 128;

    const long long p = (long long)blockIdx.x * 2 + s;
    const float* yg = y  + p * 4096;
    const float* qg = qk + p * 2048;

#pragma unroll
    for (int i = 0; i < 8; i++) {
        int idx4 = i * 128 + t;
        int m = idx4 >> 6, c = (idx4 & 63) * 4;
        cpasync16((uint32_t)__cvta_generic_to_shared(ys + m * YP + c), yg + idx4 * 4);
    }
#pragma unroll
    for (int i = 0; i < 4; i++) {
        int idx4 = i * 128 + t;
        int h = idx4 >> 6, c = (idx4 & 63) * 4;
        cpasync16((uint32_t)__cvta_generic_to_shared(qs + h * YP + c), qg + idx4 * 4);
    }
    asm volatile("cp.async.commit_group;");
    asm volatile("cp.async.wait_group 0;");
    __syncthreads();

    const int lane = t & 31, w = t >> 5;
    const int g = lane >> 2, tig = lane & 3;

    float acc[4] = {0.f, 0.f, 0.f, 0.f};
#pragma unroll
    for (int cc = 0; cc < 8; cc++) {
        const int c0 = w * 64 + cc * 8;
        float a[4], b[2];
        a[0] = ys[g * YP + c0 + tig];
        a[1] = ys[(g + 8) * YP + c0 + tig];
        a[2] = ys[g * YP + c0 + tig + 4];
        a[3] = ys[(g + 8) * YP + c0 + tig + 4];
        b[0] = qs[g * YP + c0 + tig];
        b[1] = qs[g * YP + c0 + tig + 4];

        uint32_t ah[4], al[4], bh[2], bl[2];
#pragma unroll
        for (int i = 0; i < 4; i++) {
            float hi = f2tf(a[i]);
            ah[i] = __float_as_uint(hi);
            al[i] = __float_as_uint(f2tf(a[i] - hi));
        }
#pragma unroll
        for (int i = 0; i < 2; i++) {
            float hi = f2tf(b[i]);
            bh[i] = __float_as_uint(hi);
            bl[i] = __float_as_uint(f2tf(b[i] - hi));
        }
        mma8(acc, ah, bh);
        mma8(acc, al, bh);
        mma8(acc, ah, bl);
    }
    part[w * 128 + g * 8 + 2 * tig]           = acc[0];
    part[w * 128 + g * 8 + 2 * tig + 1]       = acc[1];
    part[w * 128 + (g + 8) * 8 + 2 * tig]     = acc[2];
    part[w * 128 + (g + 8) * 8 + 2 * tig + 1] = acc[3];
    __syncthreads();

    const int h = t >> 4, m = t & 15;
    float dot = part[0 * 128 + m * 8 + h] + part[1 * 128 + m * 8 + h]
              + part[2 * 128 + m * 8 + h] + part[3 * 128 + m * 8 + h];

    float mx = dot;
#pragma unroll
    for (int o = 8; o >= 1; o >>= 1)
        mx = fmaxf(mx, __shfl_xor_sync(0xffffffffu, mx, o));
    float e = __expf(dot - mx);
    float sum = e;
#pragma unroll
    for (int o = 8; o >= 1; o >>= 1)
        sum += __shfl_xor_sync(0xffffffffu, sum, o);
    attn_s[m * 8 + h] = e / sum;
    __syncthreads();

    const int c0 = 2 * t;
    float2 acc2[8];
#pragma unroll
    for (int i = 0; i < 8; i++) acc2[i] = make_float2(0.f, 0.f);

#pragma unroll
    for (int mm = 0; mm < 16; mm++) {
        float4 a0 = *(const float4*)(attn_s + mm * 8);
        float4 a1 = *(const float4*)(attn_s + mm * 8 + 4);
        float2 yv = *(const float2*)(ys + mm * YP + c0);
        acc2[0].x = fmaf(a0.x, yv.x, acc2[0].x); acc2[0].y = fmaf(a0.x, yv.y, acc2[0].y);
        acc2[1].x = fmaf(a0.y, yv.x, acc2[1].x); acc2[1].y = fmaf(a0.y, yv.y, acc2[1].y);
        acc2[2].x = fmaf(a0.z, yv.x, acc2[2].x); acc2[2].y = fmaf(a0.z, yv.y, acc2[2].y);
        acc2[3].x = fmaf(a0.w, yv.x, acc2[3].x); acc2[3].y = fmaf(a0.w, yv.y, acc2[3].y);
        acc2[4].x = fmaf(a1.x, yv.x, acc2[4].x); acc2[4].y = fmaf(a1.x, yv.y, acc2[4].y);
        acc2[5].x = fmaf(a1.y, yv.x, acc2[5].x); acc2[5].y = fmaf(a1.y, yv.y, acc2[5].y);
        acc2[6].x = fmaf(a1.z, yv.x, acc2[6].x); acc2[6].y = fmaf(a1.z, yv.y, acc2[6].y);
        acc2[7].x = fmaf(a1.w, yv.x, acc2[7].x); acc2[7].y = fmaf(a1.w, yv.y, acc2[7].y);
    }

    float* op = ybar + p * 2048 + c0;
#pragma unroll
    for (int hh = 0; hh < 8; hh++) {
        float2 v = make_float2(f2tf(acc2[hh].x), f2tf(acc2[hh].y));
        *(float2*)(op + hh * 256) = v;
    }
}

// ================= launch: shared G1, then 2-stream pipelined halves ==========
extern "C" void kernel_launch(void* const* d_in, const int* in_sizes, int n_in,
                              void* d_out, int out_size)
{
    const float* x     = (const float*)d_in[0];
    const float* y     = (const float*)d_in[1];
    const float* W_q   = (const float*)d_in[2];
    const float* W_kv  = (const float*)d_in[3];
    const float* W_out = (const float*)d_in[4];
    const float* b_out = (const float*)d_in[5];
    float* out = (float*)d_out;

    float *qk, *ybar, *q, *v, *xt, *wqs, *wkT, *wvT, *wouT;
    cudaGetSymbolAddress((void**)&qk,   g_qk);
    cudaGetSymbolAddress((void**)&ybar, g_ybar);
    cudaGetSymbolAddress((void**)&q,    g_q);
    cudaGetSymbolAddress((void**)&v,    g_v);
    cudaGetSymbolAddress((void**)&xt,   g_xt);
    cudaGetSymbolAddress((void**)&wqs,  g_wqs);
    cudaGetSymbolAddress((void**)&wkT,  g_wkT);
    cudaGetSymbolAddress((void**)&wvT,  g_wvT);
    cudaGetSymbolAddress((void**)&wouT, g_wouT);

    const int SM128 = 2 * (A_FLOATS + BK * (128 + 8)) * 4;   // 71680
    const int SM64  = 2 * (A_FLOATS + BK * (64 + 8)) * 4;    // 55296
    cudaFuncSetAttribute(gemm4<128>, cudaFuncAttributeMaxDynamicSharedMemorySize, SM128);
    cudaFuncSetAttribute(gemm4<64>,  cudaFuncAttributeMaxDynamicSharedMemorySize, SM64);
    cudaFuncSetAttribute(gemm_k64, cudaFuncAttributeMaxDynamicSharedMemorySize, K64_SMEM);
    cudaFuncSetAttribute(attn5, cudaFuncAttributeMaxDynamicSharedMemorySize, ATTN_SMEM);

    // fork-join streams (created per call; no device-memory allocation involved)
    cudaStream_t s2;
    cudaEvent_t evG1, evDone;
    cudaStreamCreateWithFlags(&s2, cudaStreamNonBlocking);
    cudaEventCreateWithFlags(&evG1, cudaEventDisableTiming);
    cudaEventCreateWithFlags(&evDone, cudaEventDisableTiming);

    // P0: prep + shared G1 (full batch) on main stream
    prep_all<<<6144, 256>>>(W_q, W_kv, W_out, x, wqs, wkT, wvT, wouT, xt);

    // G1: q = xt @ wqs   (M=16384, N=512, K=256), round out — single full launch
    gemm4<128><<<dim3(128, 4, 1), 256, SM128>>>(xt, wqs, q, nullptr,
                                                256, 256, 512, 512, 0, 0, 0, 1);
    cudaEventRecord(evG1, 0);
    cudaStreamWaitEvent(s2, evG1, 0);

    // ---- per-half chains: half 0 on main stream, half 1 on s2 ----
    for (int half = 0; half < 2; half++) {
        cudaStream_t st = (half == 0) ? (cudaStream_t)0 : s2;
        const long long po = (long long)half * HALF_P;    // position offset

        float*       q_h    = q    + po * 512;
        float*       qk_h   = qk   + po * 2048;
        const float* y_h    = y    + po * 4096;
        float*       ybar_h = ybar + po * 2048;
        float*       v_h    = v    + po * 512;
        float*       out_h  = out  + po * 256;

        // G2: qk_h = q_h @ Wk_h^T  (per head: M=8192, N=256, K=64)
        gemm_k64<<<dim3(128, 2, 8), 256, K64_SMEM, st>>>(q_h, wkT, qk_h,
                                                         512, 256, 2048,
                                                         64, 16384, 256);

        // attn: dots -> softmax -> ybar (tf32-rounded), 2 positions per CTA
        attn5<<<HALF_P / 2, 256, ATTN_SMEM, st>>>(y_h, qk_h, ybar_h);

        // G3: v_h = ybar_h @ Wv_h  (per head: M=8192, N=64, K=256), round out
        gemm4<64><<<dim3(64, 1, 8), 256, SM64, st>>>(ybar_h, wvT, v_h, nullptr,
                                                     256, 2048, 64, 512,
                                                     256, 16384, 64, 1);

        // G4: out = v @ wouT + b_out  (M=8192, N=256, K=512)
        gemm4<128><<<dim3(64, 2, 1), 256, SM128, st>>>(v_h, wouT, out_h, b_out,
                                                       512, 512, 256, 256, 0, 0, 0, 0);
    }

    // join: main stream waits for s2's chain
    cudaEventRecord(evDone, s2);
    cudaStreamWaitEvent(0, evDone, 0);
}

// round 15
// speedup vs baseline: 1.3322x; 1.0383x over previous
#include <cuda_runtime.h>
#include <cstdint>

#define NPOS   16384
#define HALF_P (NPOS / 2)
#define SCALEF 0.125f

// -------- scratch (device globals; no allocation allowed) --------
__device__ float g_qk[(size_t)NPOS * 2048];    // 134 MB
__device__ float g_ybar[(size_t)NPOS * 2048];  // 134 MB (tf32-rounded)
__device__ float g_q [(size_t)NPOS * 512];     //  33 MB (tf32-rounded)
__device__ float g_v [(size_t)NPOS * 512];     //  33 MB (tf32-rounded)
__device__ float g_wqs [256 * 512];            // SCALE*Wq, tf32   [k=i][n]
__device__ float g_wkT [8 * 64 * 256];         // Wk^T per head    [h][d][c]
__device__ float g_wvT [8 * 256 * 64];         // Wv per head      [h][c][d]
__device__ float g_wouT[512 * 256];            // Wout, tf32       [k][n]

// ================= TF32 helpers =================
__device__ __forceinline__ float f2tf(float x) {
    uint32_t u;
    asm("cvt.rna.tf32.f32 %0, %1;" : "=r"(u) : "f"(x));
    return __uint_as_float(u);
}

__device__ __forceinline__ void mma8(float* d, const uint32_t* a, const uint32_t* b) {
    asm volatile(
        "mma.sync.aligned.m16n8k8.row.col.f32.tf32.tf32.f32 "
        "{%0,%1,%2,%3}, {%4,%5,%6,%7}, {%8,%9}, {%0,%1,%2,%3};"
        : "+f"(d[0]), "+f"(d[1]), "+f"(d[2]), "+f"(d[3])
        : "r"(a[0]), "r"(a[1]), "r"(a[2]), "r"(a[3]), "r"(b[0]), "r"(b[1]));
}

__device__ __forceinline__ void cpasync16(uint32_t s, const void* g) {
    asm volatile("cp.async.cg.shared.global [%0], [%1], 16;" :: "r"(s), "l"(g));
}

// ================= prep kernel (weights only; x consumed raw by G1) ==========
__global__ __launch_bounds__(256)
void prep_w(const float* __restrict__ Wq, const float* __restrict__ Wkv,
            const float* __restrict__ Wout,
            float* __restrict__ wqs, float* __restrict__ wkT,
            float* __restrict__ wvT, float* __restrict__ wouT)
{
    int idx = blockIdx.x * 256 + threadIdx.x;
    int sel = idx >> 17;
    int r = idx & 131071;
    if (sel == 0) {
        wqs[r] = f2tf(SCALEF * Wq[r]);                 // [i][n] n-contig
    } else if (sel == 1) {
        int h = r >> 14, d = (r >> 8) & 63, c = r & 255;
        wkT[r] = f2tf(Wkv[c * 1024 + h * 64 + d]);     // [h][d][c]
    } else if (sel == 2) {
        int h = r >> 14, c = (r >> 6) & 255, d = r & 63;
        wvT[r] = f2tf(Wkv[c * 1024 + 512 + h * 64 + d]); // [h][c][d]
    } else {
        wouT[r] = f2tf(Wout[r]);                       // [dd][j] n-contig
    }
}

// ================= TF32 GEMM (generic, 2-stage cp.async) ====================
// A fragments are tf32-rounded at load (idempotent for pre-rounded operands,
// and makes raw-fp32 A legal). B must be pre-rounded.
#define BM 128
#define BK 32
#define ASTR 36
#define A_FLOATS (BM * ASTR)        // 4608

template<int BNT>
__global__ __launch_bounds__(256, 2)
void gemm4(const float* __restrict__ A, const float* __restrict__ B,
           float* __restrict__ C, const float* __restrict__ bias,
           int K, int lda, int ldb, int ldc,
           long long aB, long long bB, long long cB, int doRound)
{
    constexpr int BSTR = BNT + 8;
    constexpr int B_FLOATS = BK * BSTR;
    constexpr int STAGEF = A_FLOATS + B_FLOATS;
    constexpr int MI = (BNT == 128) ? 4 : 2;
    constexpr int BN4 = BNT / 4;
    constexpr int NB_I = (BK * BN4) / 256;

    extern __shared__ float sm[];

    const int t = threadIdx.x;
    const int lane = t & 31, wid = t >> 5;
    const int g = lane >> 2, tig = lane & 3;
    const int wm = (BNT == 128) ? (wid & 1) * 64 : (wid & 3) * 32;
    const int wn = (BNT == 128) ? (wid >> 1) * 32 : (wid >> 2) * 32;
    const long long bm = (long long)blockIdx.x * BM;
    const long long bn = (long long)blockIdx.y * BNT;

    const float* Ab = A + (long long)blockIdx.z * aB;
    const float* Bb = B + (long long)blockIdx.z * bB + bn;
    float*       Cb = C + (long long)blockIdx.z * cB;

    uint32_t sA[2], sB[2];
#pragma unroll
    for (int s = 0; s < 2; s++) {
        sA[s] = (uint32_t)__cvta_generic_to_shared(sm + s * STAGEF);
        sB[s] = (uint32_t)__cvta_generic_to_shared(sm + s * STAGEF + A_FLOATS);
    }

    float acc[MI][4][4];
#pragma unroll
    for (int i = 0; i < MI; i++)
#pragma unroll
        for (int j = 0; j < 4; j++)
#pragma unroll
            for (int q = 0; q < 4; q++) acc[i][j][q] = 0.f;

    const int ntiles = K / BK;

#pragma unroll
    for (int i = 0; i < 4; i++) {
        int idx = i * 256 + t;
        int r = idx >> 3, c4 = idx & 7;
        cpasync16(sA[0] + (r * ASTR + c4 * 4) * 4, Ab + (bm + r) * lda + c4 * 4);
    }
#pragma unroll
    for (int i = 0; i < NB_I; i++) {
        int idx = i * 256 + t;
        int k = idx / BN4, n4 = idx % BN4;
        cpasync16(sB[0] + (k * BSTR + n4 * 4) * 4, Bb + (long long)k * ldb + n4 * 4);
    }
    asm volatile("cp.async.commit_group;");

    for (int it = 0; it < ntiles; it++) {
        const int buf = it & 1;
        if (it + 1 < ntiles) {
            const int nb = buf ^ 1;
            const long long ko = (long long)(it + 1) * BK;
#pragma unroll
            for (int i = 0; i < 4; i++) {
                int idx = i * 256 + t;
                int r = idx >> 3, c4 = idx & 7;
                cpasync16(sA[nb] + (r * ASTR + c4 * 4) * 4,
                          Ab + (bm + r) * lda + ko + c4 * 4);
            }
#pragma unroll
            for (int i = 0; i < NB_I; i++) {
                int idx = i * 256 + t;
                int k = idx / BN4, n4 = idx % BN4;
                cpasync16(sB[nb] + (k * BSTR + n4 * 4) * 4,
                          Bb + (ko + k) * ldb + n4 * 4);
            }
            asm volatile("cp.async.commit_group;");
            asm volatile("cp.async.wait_group 1;");
        } else {
            asm volatile("cp.async.wait_group 0;");
        }
        __syncthreads();

        const float* as = sm + buf * STAGEF;
        const float* bs = as + A_FLOATS;
#pragma unroll
        for (int ks = 0; ks < 4; ks++) {
            const int k0 = ks * 8;
            uint32_t af[MI][4], bf[4][2];
#pragma unroll
            for (int mi = 0; mi < MI; mi++) {
                const int r = wm + mi * 16 + g;
                af[mi][0] = __float_as_uint(f2tf(as[r * ASTR + k0 + tig]));
                af[mi][1] = __float_as_uint(f2tf(as[(r + 8) * ASTR + k0 + tig]));
                af[mi][2] = __float_as_uint(f2tf(as[r * ASTR + k0 + tig + 4]));
                af[mi][3] = __float_as_uint(f2tf(as[(r + 8) * ASTR + k0 + tig + 4]));
            }
#pragma unroll
            for (int ni = 0; ni < 4; ni++) {
                const int cn = wn + ni * 8 + g;
                bf[ni][0] = __float_as_uint(bs[(k0 + tig) * BSTR + cn]);
                bf[ni][1] = __float_as_uint(bs[(k0 + tig + 4) * BSTR + cn]);
            }
#pragma unroll
            for (int mi = 0; mi < MI; mi++)
#pragma unroll
                for (int ni = 0; ni < 4; ni++)
                    mma8(acc[mi][ni], af[mi], bf[ni]);
        }
        __syncthreads();
    }

#pragma unroll
    for (int mi = 0; mi < MI; mi++) {
#pragma unroll
        for (int ni = 0; ni < 4; ni++) {
            const long long r = bm + wm + mi * 16 + g;
            const int cn = (int)bn + wn + ni * 8 + 2 * tig;
            float v0 = acc[mi][ni][0], v1 = acc[mi][ni][1];
            float v2 = acc[mi][ni][2], v3 = acc[mi][ni][3];
            if (bias) {
                float b0 = bias[cn], b1 = bias[cn + 1];
                v0 += b0; v1 += b1; v2 += b0; v3 += b1;
            }
            if (doRound) {
                v0 = f2tf(v0); v1 = f2tf(v1); v2 = f2tf(v2); v3 = f2tf(v3);
            }
            *(float2*)(Cb + r * ldc + cn)       = make_float2(v0, v1);
            *(float2*)(Cb + (r + 8) * ldc + cn) = make_float2(v2, v3);
        }
    }
}

// ================= single-shot K=64 GEMM (G2) ================================
#define K64_ASTR 68
#define K64_BSTR 136
#define K64_AF (64 * K64_ASTR)
#define K64_BF (64 * K64_BSTR)
#define K64_SMEM ((K64_AF + K64_BF) * 4)   // 52224 bytes

__global__ __launch_bounds__(256, 3)
void gemm_k64(const float* __restrict__ A, const float* __restrict__ B,
              float* __restrict__ C,
              int lda, int ldb, int ldc,
              long long aB, long long bB, long long cB)
{
    extern __shared__ float sm[];
    float* As = sm;
    float* Bs = sm + K64_AF;

    const int t = threadIdx.x;
    const int lane = t & 31, wid = t >> 5;
    const int g = lane >> 2, tig = lane & 3;
    const int wm = (wid & 1) * 32;
    const int wn = (wid >> 1) * 32;
    const long long bm = (long long)blockIdx.x * 64;
    const long long bn = (long long)blockIdx.y * 128;

    const float* Ab = A + (long long)blockIdx.z * aB;
    const float* Bb = B + (long long)blockIdx.z * bB + bn;
    float*       Cb = C + (long long)blockIdx.z * cB;

    uint32_t sAs = (uint32_t)__cvta_generic_to_shared(As);
    uint32_t sBs = (uint32_t)__cvta_generic_to_shared(Bs);

#pragma unroll
    for (int i = 0; i < 4; i++) {
        int idx = i * 256 + t;
        int r = idx >> 4, c4 = idx & 15;
        cpasync16(sAs + (r * K64_ASTR + c4 * 4) * 4, Ab + (bm + r) * lda + c4 * 4);
    }
#pragma unroll
    for (int i = 0; i < 8; i++) {
        int idx = i * 256 + t;
        int k = idx >> 5, n4 = idx & 31;
        cpasync16(sBs + (k * K64_BSTR + n4 * 4) * 4, Bb + (long long)k * ldb + n4 * 4);
    }
    asm volatile("cp.async.commit_group;");
    asm volatile("cp.async.wait_group 0;");
    __syncthreads();

    float acc[2][4][4];
#pragma unroll
    for (int i = 0; i < 2; i++)
#pragma unroll
        for (int j = 0; j < 4; j++)
#pragma unroll
            for (int q = 0; q < 4; q++) acc[i][j][q] = 0.f;

#pragma unroll
    for (int ks = 0; ks < 8; ks++) {
        const int k0 = ks * 8;
        uint32_t af[2][4], bf[4][2];
#pragma unroll
        for (int mi = 0; mi < 2; mi++) {
            const int r = wm + mi * 16 + g;
            af[mi][0] = __float_as_uint(As[r * K64_ASTR + k0 + tig]);
            af[mi][1] = __float_as_uint(As[(r + 8) * K64_ASTR + k0 + tig]);
            af[mi][2] = __float_as_uint(As[r * K64_ASTR + k0 + tig + 4]);
            af[mi][3] = __float_as_uint(As[(r + 8) * K64_ASTR + k0 + tig + 4]);
        }
#pragma unroll
        for (int ni = 0; ni < 4; ni++) {
            const int cn = wn + ni * 8 + g;
            bf[ni][0] = __float_as_uint(Bs[(k0 + tig) * K64_BSTR + cn]);
            bf[ni][1] = __float_as_uint(Bs[(k0 + tig + 4) * K64_BSTR + cn]);
        }
#pragma unroll
        for (int mi = 0; mi < 2; mi++)
#pragma unroll
            for (int ni = 0; ni < 4; ni++)
                mma8(acc[mi][ni], af[mi], bf[ni]);
    }

#pragma unroll
    for (int mi = 0; mi < 2; mi++) {
#pragma unroll
        for (int ni = 0; ni < 4; ni++) {
            const long long r = bm + wm + mi * 16 + g;
            const int cn = (int)bn + wn + ni * 8 + 2 * tig;
            *(float2*)(Cb + r * ldc + cn) =
                make_float2(acc[mi][ni][0], acc[mi][ni][1]);
            *(float2*)(Cb + (r + 8) * ldc + cn) =
                make_float2(acc[mi][ni][2], acc[mi][ni][3]);
        }
    }
}

// ================= fused attention v5: 2 positions per CTA ====================
#define YP 260
#define YS_F (16 * YP)
#define QS_F (8 * YP)
#define ATTN_SMEM ((2 * YS_F + 2 * QS_F + 2 * 512 + 2 * 128) * 4)   // 55040 B

__global__ __launch_bounds__(256)
void attn5(const float* __restrict__ y, const float* __restrict__ qk,
           float* __restrict__ ybar)
{
    extern __shared__ float smb[];
    const int s  = threadIdx.x >> 7;
    const int t  = threadIdx.x & 127;

    float* ys     = smb + s * YS_F;
    float* qs     = smb + 2 * YS_F + s * QS_F;
    float* part   = smb + 2 * YS_F + 2 * QS_F + s * 512;
    float* attn_s = smb + 2 * YS_F + 2 * QS_F + 2 * 512 + s * 128;

    const long long p = (long long)blockIdx.x * 2 + s;
    const float* yg = y  + p * 4096;
    const float* qg = qk + p * 2048;

#pragma unroll
    for (int i = 0; i < 8; i++) {
        int idx4 = i * 128 + t;
        int m = idx4 >> 6, c = (idx4 & 63) * 4;
        cpasync16((uint32_t)__cvta_generic_to_shared(ys + m * YP + c), yg + idx4 * 4);
    }
#pragma unroll
    for (int i = 0; i < 4; i++) {
        int idx4 = i * 128 + t;
        int h = idx4 >> 6, c = (idx4 & 63) * 4;
        cpasync16((uint32_t)__cvta_generic_to_shared(qs + h * YP + c), qg + idx4 * 4);
    }
    asm volatile("cp.async.commit_group;");
    asm volatile("cp.async.wait_group 0;");
    __syncthreads();

    const int lane = t & 31, w = t >> 5;
    const int g = lane >> 2, tig = lane & 3;

    float acc[4] = {0.f, 0.f, 0.f, 0.f};
#pragma unroll
    for (int cc = 0; cc < 8; cc++) {
        const int c0 = w * 64 + cc * 8;
        float a[4], b[2];
        a[0] = ys[g * YP + c0 + tig];
        a[1] = ys[(g + 8) * YP + c0 + tig];
        a[2] = ys[g * YP + c0 + tig + 4];
        a[3] = ys[(g + 8) * YP + c0 + tig + 4];
        b[0] = qs[g * YP + c0 + tig];
        b[1] = qs[g * YP + c0 + tig + 4];

        uint32_t ah[4], al[4], bh[2], bl[2];
#pragma unroll
        for (int i = 0; i < 4; i++) {
            float hi = f2tf(a[i]);
            ah[i] = __float_as_uint(hi);
            al[i] = __float_as_uint(f2tf(a[i] - hi));
        }
#pragma unroll
        for (int i = 0; i < 2; i++) {
            float hi = f2tf(b[i]);
            bh[i] = __float_as_uint(hi);
            bl[i] = __float_as_uint(f2tf(b[i] - hi));
        }
        mma8(acc, ah, bh);
        mma8(acc, al, bh);
        mma8(acc, ah, bl);
    }
    part[w * 128 + g * 8 + 2 * tig]           = acc[0];
    part[w * 128 + g * 8 + 2 * tig + 1]       = acc[1];
    part[w * 128 + (g + 8) * 8 + 2 * tig]     = acc[2];
    part[w * 128 + (g + 8) * 8 + 2 * tig + 1] = acc[3];
    __syncthreads();

    const int h = t >> 4, m = t & 15;
    float dot = part[0 * 128 + m * 8 + h] + part[1 * 128 + m * 8 + h]
              + part[2 * 128 + m * 8 + h] + part[3 * 128 + m * 8 + h];

    float mx = dot;
#pragma unroll
    for (int o = 8; o >= 1; o >>= 1)
        mx = fmaxf(mx, __shfl_xor_sync(0xffffffffu, mx, o));
    float e = __expf(dot - mx);
    float sum = e;
#pragma unroll
    for (int o = 8; o >= 1; o >>= 1)
        sum += __shfl_xor_sync(0xffffffffu, sum, o);
    attn_s[m * 8 + h] = e / sum;
    __syncthreads();

    const int c0 = 2 * t;
    float2 acc2[8];
#pragma unroll
    for (int i = 0; i < 8; i++) acc2[i] = make_float2(0.f, 0.f);

#pragma unroll
    for (int mm = 0; mm < 16; mm++) {
        float4 a0 = *(const float4*)(attn_s + mm * 8);
        float4 a1 = *(const float4*)(attn_s + mm * 8 + 4);
        float2 yv = *(const float2*)(ys + mm * YP + c0);
        acc2[0].x = fmaf(a0.x, yv.x, acc2[0].x); acc2[0].y = fmaf(a0.x, yv.y, acc2[0].y);
        acc2[1].x = fmaf(a0.y, yv.x, acc2[1].x); acc2[1].y = fmaf(a0.y, yv.y, acc2[1].y);
        acc2[2].x = fmaf(a0.z, yv.x, acc2[2].x); acc2[2].y = fmaf(a0.z, yv.y, acc2[2].y);
        acc2[3].x = fmaf(a0.w, yv.x, acc2[3].x); acc2[3].y = fmaf(a0.w, yv.y, acc2[3].y);
        acc2[4].x = fmaf(a1.x, yv.x, acc2[4].x); acc2[4].y = fmaf(a1.x, yv.y, acc2[4].y);
        acc2[5].x = fmaf(a1.y, yv.x, acc2[5].x); acc2[5].y = fmaf(a1.y, yv.y, acc2[5].y);
        acc2[6].x = fmaf(a1.z, yv.x, acc2[6].x); acc2[6].y = fmaf(a1.z, yv.y, acc2[6].y);
        acc2[7].x = fmaf(a1.w, yv.x, acc2[7].x); acc2[7].y = fmaf(a1.w, yv.y, acc2[7].y);
    }

    float* op = ybar + p * 2048 + c0;
#pragma unroll
    for (int hh = 0; hh < 8; hh++) {
        float2 v = make_float2(f2tf(acc2[hh].x), f2tf(acc2[hh].y));
        *(float2*)(op + hh * 256) = v;
    }
}

// ================= launch: 2-stream pipelined halves (R12 structure) =========
extern "C" void kernel_launch(void* const* d_in, const int* in_sizes, int n_in,
                              void* d_out, int out_size)
{
    const float* x     = (const float*)d_in[0];
    const float* y     = (const float*)d_in[1];
    const float* W_q   = (const float*)d_in[2];
    const float* W_kv  = (const float*)d_in[3];
    const float* W_out = (const float*)d_in[4];
    const float* b_out = (const float*)d_in[5];
    float* out = (float*)d_out;

    float *qk, *ybar, *q, *v, *wqs, *wkT, *wvT, *wouT;
    cudaGetSymbolAddress((void**)&qk,   g_qk);
    cudaGetSymbolAddress((void**)&ybar, g_ybar);
    cudaGetSymbolAddress((void**)&q,    g_q);
    cudaGetSymbolAddress((void**)&v,    g_v);
    cudaGetSymbolAddress((void**)&wqs,  g_wqs);
    cudaGetSymbolAddress((void**)&wkT,  g_wkT);
    cudaGetSymbolAddress((void**)&wvT,  g_wvT);
    cudaGetSymbolAddress((void**)&wouT, g_wouT);

    const int SM128 = 2 * (A_FLOATS + BK * (128 + 8)) * 4;   // 71680
    const int SM64  = 2 * (A_FLOATS + BK * (64 + 8)) * 4;    // 55296
    cudaFuncSetAttribute(gemm4<128>, cudaFuncAttributeMaxDynamicSharedMemorySize, SM128);
    cudaFuncSetAttribute(gemm4<64>,  cudaFuncAttributeMaxDynamicSharedMemorySize, SM64);
    cudaFuncSetAttribute(gemm_k64, cudaFuncAttributeMaxDynamicSharedMemorySize, K64_SMEM);
    cudaFuncSetAttribute(attn5, cudaFuncAttributeMaxDynamicSharedMemorySize, ATTN_SMEM);

    // fork-join streams (created per call; no device-memory allocation involved)
    cudaStream_t s2;
    cudaEvent_t evPrep, evDone;
    cudaStreamCreateWithFlags(&s2, cudaStreamNonBlocking);
    cudaEventCreateWithFlags(&evPrep, cudaEventDisableTiming);
    cudaEventCreateWithFlags(&evDone, cudaEventDisableTiming);

    // P0: weight layouts only (x consumed raw by G1; A fragments tf32'd in-loop)
    prep_w<<<2048, 256>>>(W_q, W_kv, W_out, wqs, wkT, wvT, wouT);
    cudaEventRecord(evPrep, 0);
    cudaStreamWaitEvent(s2, evPrep, 0);

    // ---- per-half chains: half 0 on main stream, half 1 on s2 ----
    for (int half = 0; half < 2; half++) {
        cudaStream_t st = (half == 0) ? (cudaStream_t)0 : s2;
        const long long po = (long long)half * HALF_P;    // position offset

        const float* x_h    = x    + po * 256;
        float*       q_h    = q    + po * 512;
        float*       qk_h   = qk   + po * 2048;
        const float* y_h    = y    + po * 4096;
        float*       ybar_h = ybar + po * 2048;
        float*       v_h    = v    + po * 512;
        float*       out_h  = out  + po * 256;

        // G1: q = x @ wqs   (M=8192, N=512, K=256), round out
        gemm4<128><<<dim3(64, 4, 1), 256, SM128, st>>>(x_h, wqs, q_h, nullptr,
                                                       256, 256, 512, 512, 0, 0, 0, 1);

        // G2: qk_h = q_h @ Wk_h^T  (per head: M=8192, N=256, K=64)
        gemm_k64<<<dim3(128, 2, 8), 256, K64_SMEM, st>>>(q_h, wkT, qk_h,
                                                         512, 256, 2048,
                                                         64, 16384, 256);

        // attn: dots -> softmax -> ybar (tf32-rounded), 2 positions per CTA
        attn5<<<HALF_P / 2, 256, ATTN_SMEM, st>>>(y_h, qk_h, ybar_h);

        // G3: v_h = ybar_h @ Wv_h  (per head: M=8192, N=64, K=256), round out
        gemm4<64><<<dim3(64, 1, 8), 256, SM64, st>>>(ybar_h, wvT, v_h, nullptr,
                                                     256, 2048, 64, 512,
                                                     256, 16384, 64, 1);

        // G4: out = v @ wouT + b_out  (M=8192, N=256, K=512)
        gemm4<128><<<dim3(64, 2, 1), 256, SM128, st>>>(v_h, wouT, out_h, b_out,
                                                       512, 512, 256, 256, 0, 0, 0, 0);
    }

    // join: main stream waits for s2's chain
    cudaEventRecord(evDone, s2);
    cudaStreamWaitEvent(0, evDone, 0);
}

// round 17
// speedup vs baseline: 1.3735x; 1.0310x over previous
#include <cuda_runtime.h>
#include <cuda_fp16.h>
#include <cstdint>

#define NPOS   16384
#define HALF_P (NPOS / 2)
#define SCALEF 0.125f

// -------- scratch (device globals; no allocation allowed) --------
__device__ float  g_qk[(size_t)NPOS * 2048];    // 134 MB
__device__ __half g_ybar[(size_t)NPOS * 2048];  //  67 MB (fp16)
__device__ float  g_q [(size_t)NPOS * 512];     //  33 MB (tf32-rounded)
__device__ float  g_v [(size_t)NPOS * 512];     //  33 MB
__device__ float  g_wqs [256 * 512];            // SCALE*Wq, tf32   [k=i][n]
__device__ float  g_wkT [8 * 64 * 256];         // Wk^T per head    [h][d][c]
__device__ float  g_wvT [8 * 256 * 64];         // Wv per head      [h][c][d]
__device__ float  g_wouT[512 * 256];            // Wout, tf32       [k][n]

// ================= TF32 helpers =================
__device__ __forceinline__ float f2tf(float x) {
    uint32_t u;
    asm("cvt.rna.tf32.f32 %0, %1;" : "=r"(u) : "f"(x));
    return __uint_as_float(u);
}

__device__ __forceinline__ void mma8(float* d, const uint32_t* a, const uint32_t* b) {
    asm volatile(
        "mma.sync.aligned.m16n8k8.row.col.f32.tf32.tf32.f32 "
        "{%0,%1,%2,%3}, {%4,%5,%6,%7}, {%8,%9}, {%0,%1,%2,%3};"
        : "+f"(d[0]), "+f"(d[1]), "+f"(d[2]), "+f"(d[3])
        : "r"(a[0]), "r"(a[1]), "r"(a[2]), "r"(a[3]), "r"(b[0]), "r"(b[1]));
}

__device__ __forceinline__ void cpasync16(uint32_t s, const void* g) {
    asm volatile("cp.async.cg.shared.global [%0], [%1], 16;" :: "r"(s), "l"(g));
}

// ================= prep kernel (weights only) =================
__global__ __launch_bounds__(256)
void prep_w(const float* __restrict__ Wq, const float* __restrict__ Wkv,
            const float* __restrict__ Wout,
            float* __restrict__ wqs, float* __restrict__ wkT,
            float* __restrict__ wvT, float* __restrict__ wouT)
{
    int idx = blockIdx.x * 256 + threadIdx.x;
    int sel = idx >> 17;
    int r = idx & 131071;
    if (sel == 0) {
        wqs[r] = f2tf(SCALEF * Wq[r]);                 // [i][n] n-contig
    } else if (sel == 1) {
        int h = r >> 14, d = (r >> 8) & 63, c = r & 255;
        wkT[r] = f2tf(Wkv[c * 1024 + h * 64 + d]);     // [h][d][c]
    } else if (sel == 2) {
        int h = r >> 14, c = (r >> 6) & 255, d = r & 63;
        wvT[r] = f2tf(Wkv[c * 1024 + 512 + h * 64 + d]); // [h][c][d]
    } else {
        wouT[r] = f2tf(Wout[r]);                       // [dd][j] n-contig
    }
}

// ================= TF32 GEMM (generic, 2-stage cp.async, fp32 A) =============
// A fragments tf32-rounded at load (raw fp32 A legal). B must be pre-rounded.
#define BM 128
#define BK 32
#define ASTR 36
#define A_FLOATS (BM * ASTR)        // 4608

template<int BNT>
__global__ __launch_bounds__(256, 2)
void gemm4(const float* __restrict__ A, const float* __restrict__ B,
           float* __restrict__ C, const float* __restrict__ bias,
           int K, int lda, int ldb, int ldc,
           long long aB, long long bB, long long cB, int doRound)
{
    constexpr int BSTR = BNT + 8;
    constexpr int B_FLOATS = BK * BSTR;
    constexpr int STAGEF = A_FLOATS + B_FLOATS;
    constexpr int MI = (BNT == 128) ? 4 : 2;
    constexpr int BN4 = BNT / 4;
    constexpr int NB_I = (BK * BN4) / 256;

    extern __shared__ float sm[];

    const int t = threadIdx.x;
    const int lane = t & 31, wid = t >> 5;
    const int g = lane >> 2, tig = lane & 3;
    const int wm = (BNT == 128) ? (wid & 1) * 64 : (wid & 3) * 32;
    const int wn = (BNT == 128) ? (wid >> 1) * 32 : (wid >> 2) * 32;
    const long long bm = (long long)blockIdx.x * BM;
    const long long bn = (long long)blockIdx.y * BNT;

    const float* Ab = A + (long long)blockIdx.z * aB;
    const float* Bb = B + (long long)blockIdx.z * bB + bn;
    float*       Cb = C + (long long)blockIdx.z * cB;

    uint32_t sA[2], sB[2];
#pragma unroll
    for (int s = 0; s < 2; s++) {
        sA[s] = (uint32_t)__cvta_generic_to_shared(sm + s * STAGEF);
        sB[s] = (uint32_t)__cvta_generic_to_shared(sm + s * STAGEF + A_FLOATS);
    }

    float acc[MI][4][4];
#pragma unroll
    for (int i = 0; i < MI; i++)
#pragma unroll
        for (int j = 0; j < 4; j++)
#pragma unroll
            for (int q = 0; q < 4; q++) acc[i][j][q] = 0.f;

    const int ntiles = K / BK;

#pragma unroll
    for (int i = 0; i < 4; i++) {
        int idx = i * 256 + t;
        int r = idx >> 3, c4 = idx & 7;
        cpasync16(sA[0] + (r * ASTR + c4 * 4) * 4, Ab + (bm + r) * lda + c4 * 4);
    }
#pragma unroll
    for (int i = 0; i < NB_I; i++) {
        int idx = i * 256 + t;
        int k = idx / BN4, n4 = idx % BN4;
        cpasync16(sB[0] + (k * BSTR + n4 * 4) * 4, Bb + (long long)k * ldb + n4 * 4);
    }
    asm volatile("cp.async.commit_group;");

    for (int it = 0; it < ntiles; it++) {
        const int buf = it & 1;
        if (it + 1 < ntiles) {
            const int nb = buf ^ 1;
            const long long ko = (long long)(it + 1) * BK;
#pragma unroll
            for (int i = 0; i < 4; i++) {
                int idx = i * 256 + t;
                int r = idx >> 3, c4 = idx & 7;
                cpasync16(sA[nb] + (r * ASTR + c4 * 4) * 4,
                          Ab + (bm + r) * lda + ko + c4 * 4);
            }
#pragma unroll
            for (int i = 0; i < NB_I; i++) {
                int idx = i * 256 + t;
                int k = idx / BN4, n4 = idx % BN4;
                cpasync16(sB[nb] + (k * BSTR + n4 * 4) * 4,
                          Bb + (ko + k) * ldb + n4 * 4);
            }
            asm volatile("cp.async.commit_group;");
            asm volatile("cp.async.wait_group 1;");
        } else {
            asm volatile("cp.async.wait_group 0;");
        }
        __syncthreads();

        const float* as = sm + buf * STAGEF;
        const float* bs = as + A_FLOATS;
#pragma unroll
        for (int ks = 0; ks < 4; ks++) {
            const int k0 = ks * 8;
            uint32_t af[MI][4], bf[4][2];
#pragma unroll
            for (int mi = 0; mi < MI; mi++) {
                const int r = wm + mi * 16 + g;
                af[mi][0] = __float_as_uint(f2tf(as[r * ASTR + k0 + tig]));
                af[mi][1] = __float_as_uint(f2tf(as[(r + 8) * ASTR + k0 + tig]));
                af[mi][2] = __float_as_uint(f2tf(as[r * ASTR + k0 + tig + 4]));
                af[mi][3] = __float_as_uint(f2tf(as[(r + 8) * ASTR + k0 + tig + 4]));
            }
#pragma unroll
            for (int ni = 0; ni < 4; ni++) {
                const int cn = wn + ni * 8 + g;
                bf[ni][0] = __float_as_uint(bs[(k0 + tig) * BSTR + cn]);
                bf[ni][1] = __float_as_uint(bs[(k0 + tig + 4) * BSTR + cn]);
            }
#pragma unroll
            for (int mi = 0; mi < MI; mi++)
#pragma unroll
                for (int ni = 0; ni < 4; ni++)
                    mma8(acc[mi][ni], af[mi], bf[ni]);
        }
        __syncthreads();
    }

#pragma unroll
    for (int mi = 0; mi < MI; mi++) {
#pragma unroll
        for (int ni = 0; ni < 4; ni++) {
            const long long r = bm + wm + mi * 16 + g;
            const int cn = (int)bn + wn + ni * 8 + 2 * tig;
            float v0 = acc[mi][ni][0], v1 = acc[mi][ni][1];
            float v2 = acc[mi][ni][2], v3 = acc[mi][ni][3];
            if (bias) {
                float b0 = bias[cn], b1 = bias[cn + 1];
                v0 += b0; v1 += b1; v2 += b0; v3 += b1;
            }
            if (doRound) {
                v0 = f2tf(v0); v1 = f2tf(v1); v2 = f2tf(v2); v3 = f2tf(v3);
            }
            *(float2*)(Cb + r * ldc + cn)       = make_float2(v0, v1);
            *(float2*)(Cb + (r + 8) * ldc + cn) = make_float2(v2, v3);
        }
    }
}

// ================= fp16-A GEMM for G3 (BM=128, BN=64, 2-stage) ===============
// C[m,n] = sum_k h2f(A[m,k])*B[k,n]; A fp16 k-contig, B fp32 n-contig.
#define ASTRH 40                      // halves per A row (32 + 8 pad)
#define AH_BYTES (BM * ASTRH * 2)     // 10240
#define BH_STR 72
#define BH_BYTES (BK * BH_STR * 4)    // 9216
#define STAGEH_BYTES (AH_BYTES + BH_BYTES)   // 19456
#define GEMM4H_SMEM (2 * STAGEH_BYTES)       // 38912

__global__ __launch_bounds__(256, 2)
void gemm4h(const __half* __restrict__ A, const float* __restrict__ B,
            float* __restrict__ C,
            int K, int lda, int ldb, int ldc,
            long long aB, long long bB, long long cB)
{
    extern __shared__ char smc[];

    const int t = threadIdx.x;
    const int lane = t & 31, wid = t >> 5;
    const int g = lane >> 2, tig = lane & 3;
    const int wm = (wid & 3) * 32;
    const int wn = (wid >> 2) * 32;
    const long long bm = (long long)blockIdx.x * BM;
    const long long bn = (long long)blockIdx.y * 64;

    const __half* Ab = A + (long long)blockIdx.z * aB;
    const float*  Bb = B + (long long)blockIdx.z * bB + bn;
    float*        Cb = C + (long long)blockIdx.z * cB;

    uint32_t sA[2], sB[2];
#pragma unroll
    for (int s = 0; s < 2; s++) {
        sA[s] = (uint32_t)__cvta_generic_to_shared(smc + s * STAGEH_BYTES);
        sB[s] = (uint32_t)__cvta_generic_to_shared(smc + s * STAGEH_BYTES + AH_BYTES);
    }

    float acc[2][4][4];
#pragma unroll
    for (int i = 0; i < 2; i++)
#pragma unroll
        for (int j = 0; j < 4; j++)
#pragma unroll
            for (int q = 0; q < 4; q++) acc[i][j][q] = 0.f;

    const int ntiles = K / BK;

    // A: 128 rows x 32 halves = 512 x 16B chunks (2/thread); B: 512 chunks (2/thread)
#pragma unroll
    for (int i = 0; i < 2; i++) {
        int idx = i * 256 + t;
        int r = idx >> 2, c8 = idx & 3;
        cpasync16(sA[0] + r * (ASTRH * 2) + c8 * 16, Ab + (bm + r) * lda + c8 * 8);
    }
#pragma unroll
    for (int i = 0; i < 2; i++) {
        int idx = i * 256 + t;
        int k = idx >> 4, n4 = idx & 15;
        cpasync16(sB[0] + (k * BH_STR + n4 * 4) * 4, Bb + (long long)k * ldb + n4 * 4);
    }
    asm volatile("cp.async.commit_group;");

    for (int it = 0; it < ntiles; it++) {
        const int buf = it & 1;
        if (it + 1 < ntiles) {
            const int nb = buf ^ 1;
            const long long ko = (long long)(it + 1) * BK;
#pragma unroll
            for (int i = 0; i < 2; i++) {
                int idx = i * 256 + t;
                int r = idx >> 2, c8 = idx & 3;
                cpasync16(sA[nb] + r * (ASTRH * 2) + c8 * 16,
                          Ab + (bm + r) * lda + ko + c8 * 8);
            }
#pragma unroll
            for (int i = 0; i < 2; i++) {
                int idx = i * 256 + t;
                int k = idx >> 4, n4 = idx & 15;
                cpasync16(sB[nb] + (k * BH_STR + n4 * 4) * 4,
                          Bb + (ko + k) * ldb + n4 * 4);
            }
            asm volatile("cp.async.commit_group;");
            asm volatile("cp.async.wait_group 1;");
        } else {
            asm volatile("cp.async.wait_group 0;");
        }
        __syncthreads();

        const __half* as = (const __half*)(smc + buf * STAGEH_BYTES);
        const float*  bs = (const float*)(smc + buf * STAGEH_BYTES + AH_BYTES);
#pragma unroll
        for (int ks = 0; ks < 4; ks++) {
            const int k0 = ks * 8;
            uint32_t af[2][4], bf[4][2];
#pragma unroll
            for (int mi = 0; mi < 2; mi++) {
                const int r = wm + mi * 16 + g;
                af[mi][0] = __float_as_uint(__half2float(as[r * ASTRH + k0 + tig]));
                af[mi][1] = __float_as_uint(__half2float(as[(r + 8) * ASTRH + k0 + tig]));
                af[mi][2] = __float_as_uint(__half2float(as[r * ASTRH + k0 + tig + 4]));
                af[mi][3] = __float_as_uint(__half2float(as[(r + 8) * ASTRH + k0 + tig + 4]));
            }
#pragma unroll
            for (int ni = 0; ni < 4; ni++) {
                const int cn = wn + ni * 8 + g;
                bf[ni][0] = __float_as_uint(bs[(k0 + tig) * BH_STR + cn]);
                bf[ni][1] = __float_as_uint(bs[(k0 + tig + 4) * BH_STR + cn]);
            }
#pragma unroll
            for (int mi = 0; mi < 2; mi++)
#pragma unroll
                for (int ni = 0; ni < 4; ni++)
                    mma8(acc[mi][ni], af[mi], bf[ni]);
        }
        __syncthreads();
    }

#pragma unroll
    for (int mi = 0; mi < 2; mi++) {
#pragma unroll
        for (int ni = 0; ni < 4; ni++) {
            const long long r = bm + wm + mi * 16 + g;
            const int cn = (int)bn + wn + ni * 8 + 2 * tig;
            *(float2*)(Cb + r * ldc + cn) =
                make_float2(acc[mi][ni][0], acc[mi][ni][1]);
            *(float2*)(Cb + (r + 8) * ldc + cn) =
                make_float2(acc[mi][ni][2], acc[mi][ni][3]);
        }
    }
}

// ================= single-shot K=64 GEMM (G2) ================================
#define K64_ASTR 68
#define K64_BSTR 136
#define K64_AF (64 * K64_ASTR)
#define K64_BF (64 * K64_BSTR)
#define K64_SMEM ((K64_AF + K64_BF) * 4)   // 52224 bytes

__global__ __launch_bounds__(256, 3)
void gemm_k64(const float* __restrict__ A, const float* __restrict__ B,
              float* __restrict__ C,
              int lda, int ldb, int ldc,
              long long aB, long long bB, long long cB)
{
    extern __shared__ float sm[];
    float* As = sm;
    float* Bs = sm + K64_AF;

    const int t = threadIdx.x;
    const int lane = t & 31, wid = t >> 5;
    const int g = lane >> 2, tig = lane & 3;
    const int wm = (wid & 1) * 32;
    const int wn = (wid >> 1) * 32;
    const long long bm = (long long)blockIdx.x * 64;
    const long long bn = (long long)blockIdx.y * 128;

    const float* Ab = A + (long long)blockIdx.z * aB;
    const float* Bb = B + (long long)blockIdx.z * bB + bn;
    float*       Cb = C + (long long)blockIdx.z * cB;

    uint32_t sAs = (uint32_t)__cvta_generic_to_shared(As);
    uint32_t sBs = (uint32_t)__cvta_generic_to_shared(Bs);

#pragma unroll
    for (int i = 0; i < 4; i++) {
        int idx = i * 256 + t;
        int r = idx >> 4, c4 = idx & 15;
        cpasync16(sAs + (r * K64_ASTR + c4 * 4) * 4, Ab + (bm + r) * lda + c4 * 4);
    }
#pragma unroll
    for (int i = 0; i < 8; i++) {
        int idx = i * 256 + t;
        int k = idx >> 5, n4 = idx & 31;
        cpasync16(sBs + (k * K64_BSTR + n4 * 4) * 4, Bb + (long long)k * ldb + n4 * 4);
    }
    asm volatile("cp.async.commit_group;");
    asm volatile("cp.async.wait_group 0;");
    __syncthreads();

    float acc[2][4][4];
#pragma unroll
    for (int i = 0; i < 2; i++)
#pragma unroll
        for (int j = 0; j < 4; j++)
#pragma unroll
            for (int q = 0; q < 4; q++) acc[i][j][q] = 0.f;

#pragma unroll
    for (int ks = 0; ks < 8; ks++) {
        const int k0 = ks * 8;
        uint32_t af[2][4], bf[4][2];
#pragma unroll
        for (int mi = 0; mi < 2; mi++) {
            const int r = wm + mi * 16 + g;
            af[mi][0] = __float_as_uint(As[r * K64_ASTR + k0 + tig]);
            af[mi][1] = __float_as_uint(As[(r + 8) * K64_ASTR + k0 + tig]);
            af[mi][2] = __float_as_uint(As[r * K64_ASTR + k0 + tig + 4]);
            af[mi][3] = __float_as_uint(As[(r + 8) * K64_ASTR + k0 + tig + 4]);
        }
#pragma unroll
        for (int ni = 0; ni < 4; ni++) {
            const int cn = wn + ni * 8 + g;
            bf[ni][0] = __float_as_uint(Bs[(k0 + tig) * K64_BSTR + cn]);
            bf[ni][1] = __float_as_uint(Bs[(k0 + tig + 4) * K64_BSTR + cn]);
        }
#pragma unroll
        for (int mi = 0; mi < 2; mi++)
#pragma unroll
            for (int ni = 0; ni < 4; ni++)
                mma8(acc[mi][ni], af[mi], bf[ni]);
    }

#pragma unroll
    for (int mi = 0; mi < 2; mi++) {
#pragma unroll
        for (int ni = 0; ni < 4; ni++) {
            const long long r = bm + wm + mi * 16 + g;
            const int cn = (int)bn + wn + ni * 8 + 2 * tig;
            *(float2*)(Cb + r * ldc + cn) =
                make_float2(acc[mi][ni][0], acc[mi][ni][1]);
            *(float2*)(Cb + (r + 8) * ldc + cn) =
                make_float2(acc[mi][ni][2], acc[mi][ni][3]);
        }
    }
}

// ================= fused attention v6: fp16 ybar output =======================
#define YP 260
#define YS_F (16 * YP)
#define QS_F (8 * YP)
#define ATTN_SMEM ((2 * YS_F + 2 * QS_F + 2 * 512 + 2 * 128) * 4)   // 55040 B

__global__ __launch_bounds__(256)
void attn6(const float* __restrict__ y, const float* __restrict__ qk,
           __half* __restrict__ ybar)
{
    extern __shared__ float smb[];
    const int s  = threadIdx.x >> 7;
    const int t  = threadIdx.x & 127;

    float* ys     = smb + s * YS_F;
    float* qs     = smb + 2 * YS_F + s * QS_F;
    float* part   = smb + 2 * YS_F + 2 * QS_F + s * 512;
    float* attn_s = smb + 2 * YS_F + 2 * QS_F + 2 * 512 + s * 128;

    const long long p = (long long)blockIdx.x * 2 + s;
    const float* yg = y  + p * 4096;
    const float* qg = qk + p * 2048;

#pragma unroll
    for (int i = 0; i < 8; i++) {
        int idx4 = i * 128 + t;
        int m = idx4 >> 6, c = (idx4 & 63) * 4;
        cpasync16((uint32_t)__cvta_generic_to_shared(ys + m * YP + c), yg + idx4 * 4);
    }
#pragma unroll
    for (int i = 0; i < 4; i++) {
        int idx4 = i * 128 + t;
        int h = idx4 >> 6, c = (idx4 & 63) * 4;
        cpasync16((uint32_t)__cvta_generic_to_shared(qs + h * YP + c), qg + idx4 * 4);
    }
    asm volatile("cp.async.commit_group;");
    asm volatile("cp.async.wait_group 0;");
    __syncthreads();

    const int lane = t & 31, w = t >> 5;
    const int g = lane >> 2, tig = lane & 3;

    float acc[4] = {0.f, 0.f, 0.f, 0.f};
#pragma unroll
    for (int cc = 0; cc < 8; cc++) {
        const int c0 = w * 64 + cc * 8;
        float a[4], b[2];
        a[0] = ys[g * YP + c0 + tig];
        a[1] = ys[(g + 8) * YP + c0 + tig];
        a[2] = ys[g * YP + c0 + tig + 4];
        a[3] = ys[(g + 8) * YP + c0 + tig + 4];
        b[0] = qs[g * YP + c0 + tig];
        b[1] = qs[g * YP + c0 + tig + 4];

        uint32_t ah[4], al[4], bh[2], bl[2];
#pragma unroll
        for (int i = 0; i < 4; i++) {
            float hi = f2tf(a[i]);
            ah[i] = __float_as_uint(hi);
            al[i] = __float_as_uint(f2tf(a[i] - hi));
        }
#pragma unroll
        for (int i = 0; i < 2; i++) {
            float hi = f2tf(b[i]);
            bh[i] = __float_as_uint(hi);
            bl[i] = __float_as_uint(f2tf(b[i] - hi));
        }
        mma8(acc, ah, bh);
        mma8(acc, al, bh);
        mma8(acc, ah, bl);
    }
    part[w * 128 + g * 8 + 2 * tig]           = acc[0];
    part[w * 128 + g * 8 + 2 * tig + 1]       = acc[1];
    part[w * 128 + (g + 8) * 8 + 2 * tig]     = acc[2];
    part[w * 128 + (g + 8) * 8 + 2 * tig + 1] = acc[3];
    __syncthreads();

    const int h = t >> 4, m = t & 15;
    float dot = part[0 * 128 + m * 8 + h] + part[1 * 128 + m * 8 + h]
              + part[2 * 128 + m * 8 + h] + part[3 * 128 + m * 8 + h];

    float mx = dot;
#pragma unroll
    for (int o = 8; o >= 1; o >>= 1)
        mx = fmaxf(mx, __shfl_xor_sync(0xffffffffu, mx, o));
    float e = __expf(dot - mx);
    float sum = e;
#pragma unroll
    for (int o = 8; o >= 1; o >>= 1)
        sum += __shfl_xor_sync(0xffffffffu, sum, o);
    attn_s[m * 8 + h] = e / sum;
    __syncthreads();

    const int c0 = 2 * t;
    float2 acc2[8];
#pragma unroll
    for (int i = 0; i < 8; i++) acc2[i] = make_float2(0.f, 0.f);

#pragma unroll
    for (int mm = 0; mm < 16; mm++) {
        float4 a0 = *(const float4*)(attn_s + mm * 8);
        float4 a1 = *(const float4*)(attn_s + mm * 8 + 4);
        float2 yv = *(const float2*)(ys + mm * YP + c0);
        acc2[0].x = fmaf(a0.x, yv.x, acc2[0].x); acc2[0].y = fmaf(a0.x, yv.y, acc2[0].y);
        acc2[1].x = fmaf(a0.y, yv.x, acc2[1].x); acc2[1].y = fmaf(a0.y, yv.y, acc2[1].y);
        acc2[2].x = fmaf(a0.z, yv.x, acc2[2].x); acc2[2].y = fmaf(a0.z, yv.y, acc2[2].y);
        acc2[3].x = fmaf(a0.w, yv.x, acc2[3].x); acc2[3].y = fmaf(a0.w, yv.y, acc2[3].y);
        acc2[4].x = fmaf(a1.x, yv.x, acc2[4].x); acc2[4].y = fmaf(a1.x, yv.y, acc2[4].y);
        acc2[5].x = fmaf(a1.y, yv.x, acc2[5].x); acc2[5].y = fmaf(a1.y, yv.y, acc2[5].y);
        acc2[6].x = fmaf(a1.z, yv.x, acc2[6].x); acc2[6].y = fmaf(a1.z, yv.y, acc2[6].y);
        acc2[7].x = fmaf(a1.w, yv.x, acc2[7].x); acc2[7].y = fmaf(a1.w, yv.y, acc2[7].y);
    }

    // write ybar as fp16 (2^-11 grain, exactly representable in tf32 for G3)
    __half* op = ybar + p * 2048 + c0;
#pragma unroll
    for (int hh = 0; hh < 8; hh++) {
        *(__half2*)(op + hh * 256) = __floats2half2_rn(acc2[hh].x, acc2[hh].y);
    }
}

// ================= launch: 2-stream pipelined halves (R12/R15 structure) =====
extern "C" void kernel_launch(void* const* d_in, const int* in_sizes, int n_in,
                              void* d_out, int out_size)
{
    const float* x     = (const float*)d_in[0];
    const float* y     = (const float*)d_in[1];
    const float* W_q   = (const float*)d_in[2];
    const float* W_kv  = (const float*)d_in[3];
    const float* W_out = (const float*)d_in[4];
    const float* b_out = (const float*)d_in[5];
    float* out = (float*)d_out;

    float *qk, *q, *v, *wqs, *wkT, *wvT, *wouT;
    __half* ybar;
    cudaGetSymbolAddress((void**)&qk,   g_qk);
    cudaGetSymbolAddress((void**)&ybar, g_ybar);
    cudaGetSymbolAddress((void**)&q,    g_q);
    cudaGetSymbolAddress((void**)&v,    g_v);
    cudaGetSymbolAddress((void**)&wqs,  g_wqs);
    cudaGetSymbolAddress((void**)&wkT,  g_wkT);
    cudaGetSymbolAddress((void**)&wvT,  g_wvT);
    cudaGetSymbolAddress((void**)&wouT, g_wouT);

    const int SM128 = 2 * (A_FLOATS + BK * (128 + 8)) * 4;   // 71680
    cudaFuncSetAttribute(gemm4<128>, cudaFuncAttributeMaxDynamicSharedMemorySize, SM128);
    cudaFuncSetAttribute(gemm4h, cudaFuncAttributeMaxDynamicSharedMemorySize, GEMM4H_SMEM);
    cudaFuncSetAttribute(gemm_k64, cudaFuncAttributeMaxDynamicSharedMemorySize, K64_SMEM);
    cudaFuncSetAttribute(attn6, cudaFuncAttributeMaxDynamicSharedMemorySize, ATTN_SMEM);

    // fork-join streams (created per call; no device-memory allocation involved)
    cudaStream_t s2;
    cudaEvent_t evPrep, evDone;
    cudaStreamCreateWithFlags(&s2, cudaStreamNonBlocking);
    cudaEventCreateWithFlags(&evPrep, cudaEventDisableTiming);
    cudaEventCreateWithFlags(&evDone, cudaEventDisableTiming);

    // P0: weight layouts
    prep_w<<<2048, 256>>>(W_q, W_kv, W_out, wqs, wkT, wvT, wouT);
    cudaEventRecord(evPrep, 0);
    cudaStreamWaitEvent(s2, evPrep, 0);

    // ---- per-half chains: half 0 on main stream, half 1 on s2 ----
    for (int half = 0; half < 2; half++) {
        cudaStream_t st = (half == 0) ? (cudaStream_t)0 : s2;
        const long long po = (long long)half * HALF_P;    // position offset

        const float* x_h    = x    + po * 256;
        float*       q_h    = q    + po * 512;
        float*       qk_h   = qk   + po * 2048;
        const float* y_h    = y    + po * 4096;
        __half*      ybar_h = ybar + po * 2048;
        float*       v_h    = v    + po * 512;
        float*       out_h  = out  + po * 256;

        // G1: q = x @ wqs   (M=8192, N=512, K=256), round out
        gemm4<128><<<dim3(64, 4, 1), 256, SM128, st>>>(x_h, wqs, q_h, nullptr,
                                                       256, 256, 512, 512, 0, 0, 0, 1);

        // G2: qk_h = q_h @ Wk_h^T  (per head: M=8192, N=256, K=64)
        gemm_k64<<<dim3(128, 2, 8), 256, K64_SMEM, st>>>(q_h, wkT, qk_h,
                                                         512, 256, 2048,
                                                         64, 16384, 256);

        // attn: dots -> softmax -> ybar (fp16), 2 positions per CTA
        attn6<<<HALF_P / 2, 256, ATTN_SMEM, st>>>(y_h, qk_h, ybar_h);

        // G3: v_h = ybar_h @ Wv_h  (per head: M=8192, N=64, K=256), fp16 A
        gemm4h<<<dim3(64, 1, 8), 256, GEMM4H_SMEM, st>>>(ybar_h, wvT, v_h,
                                                         256, 2048, 64, 512,
                                                         256, 16384, 64);

        // G4: out = v @ wouT + b_out  (M=8192, N=256, K=512)
        gemm4<128><<<dim3(64, 2, 1), 256, SM128, st>>>(v_h, wouT, out_h, b_out,
                                                       512, 512, 256, 256, 0, 0, 0, 0);
    }

    // join: main stream waits for s2's chain
    cudaEventRecord(evDone, s2);
    cudaStreamWaitEvent(0, evDone, 0);
}